// round 8
// baseline (speedup 1.0000x reference)
#include <cuda_runtime.h>
#include <math.h>

#define BB 4
#define HH 48
#define WW 48
#define LL (HH*WW)      /* 2304 */
#define DM 96
#define DI 192
#define NS 16
#define RR 6
#define KK 3
#define XD 32           /* row: [B0..B15, C0..C15] */
#define BK (BB*KK)      /* 12 */
#define CH (BK*DI)      /* 2304 chains */
#define SS 64           /* scan segments */
#define LSEG (LL/SS)    /* 36 */
#define TT 32           /* spatial tokens per k_mid block */

typedef unsigned long long u64;
union F2U { float2 f; u64 u; };
union F4U { float4 f; u64 u[2]; };

__device__ __forceinline__ u64 F2P(float x, float y){ F2U t; t.f=make_float2(x,y); return t.u; }
__device__ __forceinline__ float LOF(u64 v){ F2U t; t.u=v; return t.f.x; }
__device__ __forceinline__ float HIF(u64 v){ F2U t; t.u=v; return t.f.y; }
__device__ __forceinline__ u64 fma2(u64 a,u64 b,u64 c){ u64 d; asm("fma.rn.f32x2 %0,%1,%2,%3;":"=l"(d):"l"(a),"l"(b),"l"(c)); return d; }
__device__ __forceinline__ u64 mul2(u64 a,u64 b){ u64 d; asm("mul.rn.f32x2 %0,%1,%2;":"=l"(d):"l"(a),"l"(b)); return d; }
__device__ __forceinline__ int  ld_acq(const int* p){ int v; asm volatile("ld.global.acquire.gpu.b32 %0,[%1];":"=r"(v):"l"(p):"memory"); return v; }
__device__ __forceinline__ void st_rel(int* p, int v){ asm volatile("st.global.release.gpu.b32 [%0],%1;"::"l"(p),"r"(v):"memory"); }

/* ---------------- scratch ---------------- */
__device__ float  g_xcraw[BB*LL*DI];
__device__ float  g_z    [BB*LL*DI];
__device__ float  g_xch  [BB*LL*DI];
__device__ float  g_xdbl [BB*KK*LL*XD];
__device__ float2 g_pre  [(size_t)BB*KK*LL*DI];   /* {e1, dt*u}  [bk][l][d] */
__device__ float  g_segq [SS][NS][CH];
__device__ float  g_segp [SS][CH];
__device__ int    g_flag [BK][SS];
__device__ float  g_ys   [KK][BB*LL*DI];

__device__ __forceinline__ float fsilu(float v){ return v / (1.f + __expf(-v)); }

/* ------------- in_proj ------------- */
__global__ void k_inproj(const float* __restrict__ x, const float* __restrict__ w)
{
    __shared__ float xt[16*DM];
    int tb = blockIdx.x * 16;
    for (int i=threadIdx.x;i<16*DM;i+=blockDim.x) xt[i]=x[(size_t)tb*DM+i];
    __syncthreads();
    int j = threadIdx.x;
    u64 acc[16];
#pragma unroll
    for(int t=0;t<16;t++) acc[t]=0ull;
    const float4* w4 = reinterpret_cast<const float4*>(w + j*DM);
#pragma unroll
    for(int c4=0;c4<DM/4;c4++){
        F4U wv; wv.f = w4[c4];
#pragma unroll
        for(int t=0;t<16;t++){
            F4U xv; xv.f = *reinterpret_cast<const float4*>(&xt[t*DM+c4*4]);
            acc[t]=fma2(wv.u[0],xv.u[0],acc[t]);
            acc[t]=fma2(wv.u[1],xv.u[1],acc[t]);
        }
    }
    if(j<DI){
#pragma unroll
        for(int t=0;t<16;t++) g_xcraw[(size_t)(tb+t)*DI+j]=LOF(acc[t])+HIF(acc[t]);
    } else {
        int jz=j-DI;
#pragma unroll
        for(int t=0;t<16;t++) g_z[(size_t)(tb+t)*DI+jz]=fsilu(LOF(acc[t])+HIF(acc[t]));
    }
}

/* ------------- fused conv + x_proj + dt_proj + delta (also zeroes scan flags) ------------- */
__global__ __launch_bounds__(256) void k_mid(
    const float* __restrict__ cw, const float* __restrict__ cb,
    const float* __restrict__ xw,
    const float* __restrict__ dtw_g, const float* __restrict__ dtb_g,
    const float* __restrict__ alog)
{
    __shared__ float sxc[TT*DI];
    __shared__ float stage[KK*TT][40];
    int b  = blockIdx.y;
    int l0 = blockIdx.x * TT;
    int tid = threadIdx.x;

    if (blockIdx.x==0 && blockIdx.y==0){
        for(int i=tid;i<BK*SS;i+=256) (&g_flag[0][0])[i]=0;
    }

    if (tid < DI){
        int d = tid;
        float wt[9];
#pragma unroll
        for(int i=0;i<9;i++) wt[i]=cw[d*9+i];
        float bias=cb[d];
        const float* base = g_xcraw + (size_t)b*LL*DI + d;
        float* xo = g_xch + ((size_t)b*LL + l0)*DI + d;
#pragma unroll 4
        for(int t=0;t<TT;t++){
            int l=l0+t, h=l/WW, w0=l%WW;
            float s=bias;
#pragma unroll
            for(int kh=0;kh<3;kh++){
                int h2=h+kh-1;
                if((unsigned)h2>=HH) continue;
#pragma unroll
                for(int kw=0;kw<3;kw++){
                    int w2=w0+kw-1;
                    if((unsigned)w2>=WW) continue;
                    s += base[(size_t)(h2*WW+w2)*DI]*wt[kh*3+kw];
                }
            }
            float v=fsilu(s);
            sxc[t*DI+d]=v;
            xo[(size_t)t*DI]=v;
        }
    }
    __syncthreads();

    if (tid < 228){
        int j = tid % 114;
        int t0 = (tid >= 114) ? 16 : 0;
        int k = j/38, c = j%38;
        u64 acc[16];
#pragma unroll
        for(int t=0;t<16;t++) acc[t]=0ull;
        const float4* w4 = reinterpret_cast<const float4*>(xw + (size_t)(k*38+c)*DI);
        for(int d4=0; d4<DI/4; d4++){
            F4U wv; wv.f=w4[d4];
#pragma unroll
            for(int t=0;t<16;t++){
                F4U xv; xv.f=*reinterpret_cast<const float4*>(&sxc[(t0+t)*DI+d4*4]);
                acc[t]=fma2(wv.u[0],xv.u[0],acc[t]);
                acc[t]=fma2(wv.u[1],xv.u[1],acc[t]);
            }
        }
        int slot = (c<RR)? c : (c<RR+NS ? 8+(c-RR) : 24+(c-RR-NS));
#pragma unroll
        for(int t=0;t<16;t++) stage[k*TT+t0+t][slot]=LOF(acc[t])+HIF(acc[t]);
    }
    __syncthreads();

    if (tid < DI){
        int d = tid;
#pragma unroll
        for(int k=0;k<KK;k++){
            float dtw[RR];
#pragma unroll
            for(int r=0;r<RR;r++) dtw[r]=dtw_g[(size_t)(k*DI+d)*RR+r];
            float bias=dtb_g[k*DI+d];
            float A0 = -__expf(alog[(size_t)(k*DI+d)*NS]);
            float2* pb = g_pre + ((size_t)(b*KK+k)*LL)*DI + d;
#pragma unroll 4
            for(int t=0;t<TT;t++){
                int lsp=l0+t;
                int p = (k==0)? lsp : (k==1 ? (lsp%WW)*HH + lsp/WW : LL-1-lsp);
                float s=bias;
#pragma unroll
                for(int r=0;r<RR;r++) s += dtw[r]*stage[k*TT+t][r];
                float dt = fmaxf(s,0.f) + __logf(1.f + __expf(-fabsf(s)));
                float e1 = __expf(dt * A0);
                pb[(size_t)p*DI] = make_float2(e1, dt*sxc[t*DI+d]);
            }
        }
    }

    for(int i=tid; i<KK*TT*XD; i+=256){
        int row=i/XD, j=i%XD;
        int k=row/TT, t=row%TT;
        int lsp=l0+t;
        int p = (k==0)? lsp : (k==1 ? (lsp%WW)*HH + lsp/WW : LL-1-lsp);
        g_xdbl[((size_t)(b*KK+k)*LL+p)*XD + j] = stage[row][8+j];
    }
}

/* tree powers: a[j] = (e1^(2j+1), e1^(2j+2)) */
__device__ __forceinline__ void tree_pow(float e1, u64 a[8]){
    float e2=e1*e1, e4=e2*e2, e8=e4*e4;
    u64 e2p=F2P(e2,e2), e4p=F2P(e4,e4), e8p=F2P(e8,e8);
    a[0]=F2P(e1,e2);
    a[1]=mul2(a[0],e2p);
    a[2]=mul2(a[0],e4p);
    a[3]=mul2(a[1],e4p);
    a[4]=mul2(a[0],e8p);
    a[5]=mul2(a[1],e8p);
    a[6]=mul2(a[2],e8p);
    a[7]=mul2(a[3],e8p);
}

/* decay powers for all 16 states, unit fast path or generic fallback */
__device__ __forceinline__ void decay_pow(bool unit, float e1,
                                          const float* __restrict__ ar, float a0,
                                          u64 a[8]){
    if (unit){
        tree_pow(e1, a);
    } else {
        float lg=__log2f(e1);
#pragma unroll
        for(int j=0;j<8;j++){
            float r0=__expf(ar[2*j]-a0),  p0=exp2f(lg*r0);
            float r1=__expf(ar[2*j+1]-a0),p1=exp2f(lg*r1);
            a[j]=F2P(p0,p1);
        }
    }
}

/* ------------- fused scan: pass1 + decoupled lookback + pass2 ------------- */
__global__ __launch_bounds__(DI, 6) void k_scan(const float* __restrict__ alog)
{
    __shared__ float sb[LSEG*32];
    int seg=blockIdx.x, bk=blockIdx.y;
    int d=threadIdx.x;
    int chain=bk*DI+d;
    int k=bk%KK, b=bk/KK;
    int l0=seg*LSEG;
    {
        const float4* src = reinterpret_cast<const float4*>(g_xdbl + ((size_t)bk*LL + l0)*XD);
        for(int i=threadIdx.x;i<LSEG*8;i+=blockDim.x)
            reinterpret_cast<float4*>(sb)[i]=src[i];
    }
    __syncthreads();

    const float* ar=alog+(size_t)(k*DI+d)*NS;
    float a0=ar[0];
    bool unit=true;
#pragma unroll
    for(int n=0;n<NS;n++){
        float r=__expf(ar[n]-a0);
        unit = unit && (fabsf(r-(float)(n+1))<1e-3f);
    }
    const float2* pre=g_pre+(size_t)bk*LL*DI+d;

    /* ---- pass 1: local segment summary with h0 = 0 ---- */
    {
        float pe=1.f;
        u64 h2[8];
#pragma unroll
        for(int j=0;j<8;j++) h2[j]=0ull;
#pragma unroll 2
        for(int i=0;i<LSEG;i++){
            float2 ed = pre[(size_t)(l0+i)*DI];
            pe*=ed.x;
            u64 du2=F2P(ed.y,ed.y);
            u64 a[8]; decay_pow(unit, ed.x, ar, a0, a);
            const F4U* bp=reinterpret_cast<const F4U*>(&sb[i*32]);
#pragma unroll
            for(int j=0;j<4;j++){
                F4U bv=bp[j];
                h2[2*j]  = fma2(a[2*j],  h2[2*j],  mul2(du2,bv.u[0]));
                h2[2*j+1]= fma2(a[2*j+1],h2[2*j+1],mul2(du2,bv.u[1]));
            }
        }
#pragma unroll
        for(int j=0;j<8;j++){
            g_segq[seg][2*j][chain]  =LOF(h2[j]);
            g_segq[seg][2*j+1][chain]=HIF(h2[j]);
        }
        g_segp[seg][chain]=pe;
    }
    __threadfence();
    __syncthreads();
    if (threadIdx.x==0) st_rel(&g_flag[bk][seg], 1);

    /* ---- decoupled lookback over predecessors (backward combine) ---- */
    u64 hI[8], c2[8];
    u64 one2 = F2P(1.f,1.f);
#pragma unroll
    for(int j=0;j<8;j++){ hI[j]=0ull; c2[j]=one2; }
    {
        int j = seg-1;
        while (j >= 0){
            int cnt = (j+1 < 8) ? (j+1) : 8;
            if (threadIdx.x==0){
                for(int t=0;t<cnt;t++)
                    while (ld_acq(&g_flag[bk][j-t])==0) {}
            }
            __syncthreads();
            for(int t=0;t<cnt;t++){
                int jj = j-t;
                float pj = g_segp[jj][chain];
                u64 a[8]; decay_pow(unit, pj, ar, a0, a);
#pragma unroll
                for(int j8=0;j8<8;j8++){
                    u64 q = F2P(g_segq[jj][2*j8][chain], g_segq[jj][2*j8+1][chain]);
                    hI[j8]=fma2(c2[j8], q, hI[j8]);
                    c2[j8]=mul2(c2[j8], a[j8]);
                }
            }
            j -= cnt;
        }
    }

    /* ---- pass 2: rescan with h_init, emit y ---- */
    float* yout=g_ys[k]+(size_t)b*LL*DI+d;
    int hh=l0%HH, wc=l0/HH;
#pragma unroll 2
    for(int i=0;i<LSEG;i++){
        float2 ed=pre[(size_t)(l0+i)*DI];
        u64 du2=F2P(ed.y,ed.y);
        u64 a[8]; decay_pow(unit, ed.x, ar, a0, a);
        const F4U* bp=reinterpret_cast<const F4U*>(&sb[i*32]);
        const F4U* cp=reinterpret_cast<const F4U*>(&sb[i*32+16]);
        u64 ya=0ull, yb=0ull;
#pragma unroll
        for(int j=0;j<4;j++){
            F4U bv=bp[j]; F4U cv=cp[j];
            hI[2*j]  =fma2(a[2*j],  hI[2*j],  mul2(du2,bv.u[0])); ya=fma2(hI[2*j],  cv.u[0],ya);
            hI[2*j+1]=fma2(a[2*j+1],hI[2*j+1],mul2(du2,bv.u[1])); yb=fma2(hI[2*j+1],cv.u[1],yb);
        }
        float y=LOF(ya)+HIF(ya)+LOF(yb)+HIF(yb);
        int l=l0+i, pos;
        if(k==0) pos=l;
        else if(k==1){ pos=hh*WW+wc; hh++; if(hh==HH){hh=0;wc++;} }
        else pos=LL-1-l;
        yout[(size_t)pos*DI]=y;
    }
}

/* ------------- merge + D-term + gating + out_proj ------------- */
__global__ void k_out(const float* __restrict__ ow, const float* __restrict__ Ds,
                      float* __restrict__ out)
{
    __shared__ float yz[16*DI];
    int tb=blockIdx.x*16;
    size_t base=(size_t)tb*DI;
    for(int i=threadIdx.x;i<16*DI;i+=blockDim.x){
        int dd=i%DI;
        float dsum=Ds[dd]+Ds[DI+dd]+Ds[2*DI+dd];
        float v=g_ys[0][base+i]+g_ys[1][base+i]+g_ys[2][base+i]+dsum*g_xch[base+i];
        yz[i]=v*g_z[base+i];
    }
    __syncthreads();
    int j=threadIdx.x;
    if(j<DM){
        u64 acc[16];
#pragma unroll
        for(int t=0;t<16;t++) acc[t]=0ull;
        const float4* w4=reinterpret_cast<const float4*>(ow+(size_t)j*DI);
        for(int d4=0;d4<DI/4;d4++){
            F4U wv; wv.f=w4[d4];
#pragma unroll
            for(int t=0;t<16;t++){
                F4U xv; xv.f=*reinterpret_cast<const float4*>(&yz[t*DI+d4*4]);
                acc[t]=fma2(wv.u[0],xv.u[0],acc[t]);
                acc[t]=fma2(wv.u[1],xv.u[1],acc[t]);
            }
        }
#pragma unroll
        for(int t=0;t<16;t++) out[(size_t)(tb+t)*DM+j]=LOF(acc[t])+HIF(acc[t]);
    }
}

/* ---------------- launcher ---------------- */
extern "C" void kernel_launch(void* const* d_in, const int* in_sizes, int n_in,
                              void* d_out, int out_size)
{
    const float* x    = (const float*)d_in[0];
    const float* inw  = (const float*)d_in[2];
    const float* cw   = (const float*)d_in[3];
    const float* cb   = (const float*)d_in[4];
    const float* xw   = (const float*)d_in[5];
    const float* dtw  = (const float*)d_in[6];
    const float* dtb  = (const float*)d_in[7];
    const float* alog = (const float*)d_in[8];
    const float* Ds   = (const float*)d_in[9];
    const float* ow   = (const float*)d_in[10];
    float* out = (float*)d_out;

    k_inproj<<<BB*LL/16, 384>>>(x, inw);
    k_mid   <<<dim3(LL/TT, BB), 256>>>(cw, cb, xw, dtw, dtb, alog);
    k_scan  <<<dim3(SS, BK), DI>>>(alog);
    k_out   <<<BB*LL/16, 128>>>(ow, Ds, out);
}

// round 9
// speedup vs baseline: 1.3160x; 1.3160x over previous
#include <cuda_runtime.h>
#include <math.h>

#define BB 4
#define HH 48
#define WW 48
#define LL (HH*WW)      /* 2304 */
#define DM 96
#define DI 192
#define NS 16
#define RR 6
#define KK 3
#define XD 32           /* row: [B0..B15, C0..C15] */
#define CH (BB*KK*DI)   /* 2304 chains */
#define SS 64           /* scan segments */
#define LSEG (LL/SS)    /* 36 */
#define TT 32           /* spatial tokens per k_mid block */

typedef unsigned long long u64;
union F2U { float2 f; u64 u; };
union F4U { float4 f; u64 u[2]; };

__device__ __forceinline__ u64 F2P(float x, float y){ F2U t; t.f=make_float2(x,y); return t.u; }
__device__ __forceinline__ float LOF(u64 v){ F2U t; t.u=v; return t.f.x; }
__device__ __forceinline__ float HIF(u64 v){ F2U t; t.u=v; return t.f.y; }
__device__ __forceinline__ u64 fma2(u64 a,u64 b,u64 c){ u64 d; asm("fma.rn.f32x2 %0,%1,%2,%3;":"=l"(d):"l"(a),"l"(b),"l"(c)); return d; }
__device__ __forceinline__ u64 mul2(u64 a,u64 b){ u64 d; asm("mul.rn.f32x2 %0,%1,%2;":"=l"(d):"l"(a),"l"(b)); return d; }

/* ---------------- scratch ---------------- */
__device__ float  g_xcraw[BB*LL*DI];
__device__ float  g_z    [BB*LL*DI];
__device__ float  g_xch  [BB*LL*DI];
__device__ float  g_xdbl [BB*KK*LL*XD];
__device__ float2 g_pre  [(size_t)BB*KK*LL*DI];   /* {e1, dt*u}  [bk][l][d] */
__device__ float  g_segq [SS][NS][CH];
__device__ float  g_segp [SS][CH];
__device__ float  g_hin  [SS][NS][CH];
__device__ float  g_ys   [KK][BB*LL*DI];

__device__ __forceinline__ float fsilu(float v){ return v / (1.f + __expf(-v)); }

/* ------------- in_proj ------------- */
__global__ void k_inproj(const float* __restrict__ x, const float* __restrict__ w)
{
    __shared__ float xt[16*DM];
    int tb = blockIdx.x * 16;
    for (int i=threadIdx.x;i<16*DM;i+=blockDim.x) xt[i]=x[(size_t)tb*DM+i];
    __syncthreads();
    int j = threadIdx.x;
    u64 acc[16];
#pragma unroll
    for(int t=0;t<16;t++) acc[t]=0ull;
    const float4* w4 = reinterpret_cast<const float4*>(w + j*DM);
#pragma unroll
    for(int c4=0;c4<DM/4;c4++){
        F4U wv; wv.f = w4[c4];
#pragma unroll
        for(int t=0;t<16;t++){
            F4U xv; xv.f = *reinterpret_cast<const float4*>(&xt[t*DM+c4*4]);
            acc[t]=fma2(wv.u[0],xv.u[0],acc[t]);
            acc[t]=fma2(wv.u[1],xv.u[1],acc[t]);
        }
    }
    if(j<DI){
#pragma unroll
        for(int t=0;t<16;t++) g_xcraw[(size_t)(tb+t)*DI+j]=LOF(acc[t])+HIF(acc[t]);
    } else {
        int jz=j-DI;
#pragma unroll
        for(int t=0;t<16;t++) g_z[(size_t)(tb+t)*DI+jz]=fsilu(LOF(acc[t])+HIF(acc[t]));
    }
}

/* ------------- fused conv + x_proj + dt_proj + delta ------------- */
__global__ __launch_bounds__(256) void k_mid(
    const float* __restrict__ cw, const float* __restrict__ cb,
    const float* __restrict__ xw,
    const float* __restrict__ dtw_g, const float* __restrict__ dtb_g,
    const float* __restrict__ alog)
{
    __shared__ float sxc[TT*DI];
    __shared__ float stage[KK*TT][40];
    int b  = blockIdx.y;
    int l0 = blockIdx.x * TT;
    int tid = threadIdx.x;

    if (tid < DI){
        int d = tid;
        float wt[9];
#pragma unroll
        for(int i=0;i<9;i++) wt[i]=cw[d*9+i];
        float bias=cb[d];
        const float* base = g_xcraw + (size_t)b*LL*DI + d;
        float* xo = g_xch + ((size_t)b*LL + l0)*DI + d;
#pragma unroll 4
        for(int t=0;t<TT;t++){
            int l=l0+t, h=l/WW, w0=l%WW;
            float s=bias;
#pragma unroll
            for(int kh=0;kh<3;kh++){
                int h2=h+kh-1;
                if((unsigned)h2>=HH) continue;
#pragma unroll
                for(int kw=0;kw<3;kw++){
                    int w2=w0+kw-1;
                    if((unsigned)w2>=WW) continue;
                    s += base[(size_t)(h2*WW+w2)*DI]*wt[kh*3+kw];
                }
            }
            float v=fsilu(s);
            sxc[t*DI+d]=v;
            xo[(size_t)t*DI]=v;
        }
    }
    __syncthreads();

    if (tid < 228){
        int j = tid % 114;
        int t0 = (tid >= 114) ? 16 : 0;
        int k = j/38, c = j%38;
        u64 acc[16];
#pragma unroll
        for(int t=0;t<16;t++) acc[t]=0ull;
        const float4* w4 = reinterpret_cast<const float4*>(xw + (size_t)(k*38+c)*DI);
        for(int d4=0; d4<DI/4; d4++){
            F4U wv; wv.f=w4[d4];
#pragma unroll
            for(int t=0;t<16;t++){
                F4U xv; xv.f=*reinterpret_cast<const float4*>(&sxc[(t0+t)*DI+d4*4]);
                acc[t]=fma2(wv.u[0],xv.u[0],acc[t]);
                acc[t]=fma2(wv.u[1],xv.u[1],acc[t]);
            }
        }
        int slot = (c<RR)? c : (c<RR+NS ? 8+(c-RR) : 24+(c-RR-NS));
#pragma unroll
        for(int t=0;t<16;t++) stage[k*TT+t0+t][slot]=LOF(acc[t])+HIF(acc[t]);
    }
    __syncthreads();

    if (tid < DI){
        int d = tid;
#pragma unroll
        for(int k=0;k<KK;k++){
            float dtw[RR];
#pragma unroll
            for(int r=0;r<RR;r++) dtw[r]=dtw_g[(size_t)(k*DI+d)*RR+r];
            float bias=dtb_g[k*DI+d];
            float A0 = -__expf(alog[(size_t)(k*DI+d)*NS]);
            float2* pb = g_pre + ((size_t)(b*KK+k)*LL)*DI + d;
#pragma unroll 4
            for(int t=0;t<TT;t++){
                int lsp=l0+t;
                int p = (k==0)? lsp : (k==1 ? (lsp%WW)*HH + lsp/WW : LL-1-lsp);
                float s=bias;
#pragma unroll
                for(int r=0;r<RR;r++) s += dtw[r]*stage[k*TT+t][r];
                float dt = fmaxf(s,0.f) + __logf(1.f + __expf(-fabsf(s)));
                float e1 = __expf(dt * A0);
                pb[(size_t)p*DI] = make_float2(e1, dt*sxc[t*DI+d]);
            }
        }
    }

    for(int i=tid; i<KK*TT*XD; i+=256){
        int row=i/XD, j=i%XD;
        int k=row/TT, t=row%TT;
        int lsp=l0+t;
        int p = (k==0)? lsp : (k==1 ? (lsp%WW)*HH + lsp/WW : LL-1-lsp);
        g_xdbl[((size_t)(b*KK+k)*LL+p)*XD + j] = stage[row][8+j];
    }
}

/* tree powers: a[j] = (e1^(2j+1), e1^(2j+2)) */
__device__ __forceinline__ void tree_pow(float e1, u64 a[8]){
    float e2=e1*e1, e4=e2*e2, e8=e4*e4;
    u64 e2p=F2P(e2,e2), e4p=F2P(e4,e4), e8p=F2P(e8,e8);
    a[0]=F2P(e1,e2);
    a[1]=mul2(a[0],e2p);
    a[2]=mul2(a[0],e4p);
    a[3]=mul2(a[1],e4p);
    a[4]=mul2(a[0],e8p);
    a[5]=mul2(a[1],e8p);
    a[6]=mul2(a[2],e8p);
    a[7]=mul2(a[3],e8p);
}

/* ------------- scan pass 1: segment summaries, h0=0 ------------- */
__global__ __launch_bounds__(DI, 6) void k_scan1(const float* __restrict__ alog)
{
    __shared__ float sb[LSEG*32];
    int seg = blockIdx.x, bk = blockIdx.y;
    int d = threadIdx.x;
    int chain = bk*DI + d;
    int k = bk % KK;
    int l0 = seg*LSEG;
    {
        const float4* src = reinterpret_cast<const float4*>(g_xdbl + ((size_t)bk*LL + l0)*XD);
        for(int i=threadIdx.x;i<LSEG*8;i+=blockDim.x)
            reinterpret_cast<float4*>(sb)[i]=src[i];
    }
    __syncthreads();

    const float* ar = alog + (size_t)(k*DI+d)*NS;
    float a0 = ar[0];
    bool unit=true;
#pragma unroll
    for(int n=0;n<NS;n++){
        float r=__expf(ar[n]-a0);
        unit = unit && (fabsf(r-(float)(n+1))<1e-3f);
    }
    bool wunit = __all_sync(0xffffffffu, unit);
    const float2* pre = g_pre + (size_t)bk*LL*DI + d;
    float pe=1.f;
    if(wunit){
        u64 h2[8];
#pragma unroll
        for(int j=0;j<8;j++) h2[j]=0ull;
#pragma unroll 2
        for(int i=0;i<LSEG;i++){
            float2 ed = pre[(size_t)(l0+i)*DI];
            pe*=ed.x;
            u64 du2=F2P(ed.y,ed.y);
            u64 a[8]; tree_pow(ed.x, a);
            const F4U* bp=reinterpret_cast<const F4U*>(&sb[i*32]);
#pragma unroll
            for(int j=0;j<4;j++){
                F4U bv=bp[j];
                h2[2*j]  = fma2(a[2*j],  h2[2*j],  mul2(du2,bv.u[0]));
                h2[2*j+1]= fma2(a[2*j+1],h2[2*j+1],mul2(du2,bv.u[1]));
            }
        }
#pragma unroll
        for(int j=0;j<8;j++){
            g_segq[seg][2*j][chain]  =LOF(h2[j]);
            g_segq[seg][2*j+1][chain]=HIF(h2[j]);
        }
    } else {
        float rn[NS], h[NS];
#pragma unroll
        for(int n=0;n<NS;n++){ rn[n]=__expf(ar[n]-a0); h[n]=0.f; }
        for(int i=0;i<LSEG;i++){
            float2 ed=pre[(size_t)(l0+i)*DI];
            pe*=ed.x;
            float lg=__log2f(ed.x), du=ed.y;
#pragma unroll
            for(int n=0;n<NS;n++)
                h[n]=exp2f(lg*rn[n])*h[n] + du*sb[i*32+n];
        }
#pragma unroll
        for(int n=0;n<NS;n++) g_segq[seg][n][chain]=h[n];
    }
    g_segp[seg][chain]=pe;
}

/* ------------- combine: MUFU-free powers, deep unroll for MLP ------------- */
__global__ __launch_bounds__(256) void k_comb(const float* __restrict__ alog)
{
    int t = blockIdx.x*blockDim.x + threadIdx.x;   /* CH*NS threads */
    int n = t / CH, chain = t % CH;
    int d = chain % DI, k = (chain / DI) % KK;
    const float* ar = alog + (size_t)(k*DI+d)*NS;
    float ratio = __expf(ar[n] - ar[0]);
    float rf = rintf(ratio);
    int   m  = (int)rf;
    bool exact = (fabsf(ratio-rf) < 1e-3f) && m >= 1 && m <= 31;
    float h = 0.f;
    g_hin[0][n][chain] = 0.f;
    if (exact){
#pragma unroll 7
        for (int s=1;s<SS;s++){
            float pe = __ldg(&g_segp[s-1][chain]);
            float q  = __ldg(&g_segq[s-1][n][chain]);
            float pe2=pe*pe, pe4=pe2*pe2, pe8=pe4*pe4, pe16=pe8*pe8;
            float p1 = (m&1)? pe : 1.f;
            if(m&2)  p1*=pe2;
            if(m&4)  p1*=pe4;
            if(m&8)  p1*=pe8;
            if(m&16) p1*=pe16;
            h = p1*h + q;
            g_hin[s][n][chain] = h;
        }
    } else {
#pragma unroll 7
        for (int s=1;s<SS;s++){
            float pe = __ldg(&g_segp[s-1][chain]);
            float q  = __ldg(&g_segq[s-1][n][chain]);
            h = exp2f(__log2f(pe)*ratio)*h + q;
            g_hin[s][n][chain] = h;
        }
    }
}

/* ------------- scan pass 2: rescan with h_init, emit y ------------- */
__global__ __launch_bounds__(DI, 6) void k_scan2(const float* __restrict__ alog)
{
    __shared__ float sb[LSEG*32];
    int seg=blockIdx.x, bk=blockIdx.y;
    int d=threadIdx.x;
    int chain=bk*DI+d;
    int k=bk%KK, b=bk/KK;
    int l0=seg*LSEG;
    {
        const float4* src = reinterpret_cast<const float4*>(g_xdbl + ((size_t)bk*LL + l0)*XD);
        for(int i=threadIdx.x;i<LSEG*8;i+=blockDim.x)
            reinterpret_cast<float4*>(sb)[i]=src[i];
    }
    __syncthreads();
    const float* ar=alog+(size_t)(k*DI+d)*NS;
    float a0=ar[0];
    bool unit=true;
#pragma unroll
    for(int n=0;n<NS;n++){ float r=__expf(ar[n]-a0); unit=unit&&(fabsf(r-(float)(n+1))<1e-3f); }
    bool wunit=__all_sync(0xffffffffu,unit);
    const float2* pre=g_pre+(size_t)bk*LL*DI+d;
    float* yout=g_ys[k]+(size_t)b*LL*DI+d;
    int hh=l0%HH, wc=l0/HH;
    if(wunit){
        u64 h2[8];
#pragma unroll
        for(int j=0;j<8;j++) h2[j]=F2P(g_hin[seg][2*j][chain], g_hin[seg][2*j+1][chain]);
#pragma unroll 2
        for(int i=0;i<LSEG;i++){
            float2 ed=pre[(size_t)(l0+i)*DI];
            u64 du2=F2P(ed.y,ed.y);
            u64 a[8]; tree_pow(ed.x, a);
            const F4U* bp=reinterpret_cast<const F4U*>(&sb[i*32]);
            const F4U* cp=reinterpret_cast<const F4U*>(&sb[i*32+16]);
            u64 ya=0ull, yb=0ull;
#pragma unroll
            for(int j=0;j<4;j++){
                F4U bv=bp[j]; F4U cv=cp[j];
                h2[2*j]  =fma2(a[2*j],  h2[2*j],  mul2(du2,bv.u[0])); ya=fma2(h2[2*j],  cv.u[0],ya);
                h2[2*j+1]=fma2(a[2*j+1],h2[2*j+1],mul2(du2,bv.u[1])); yb=fma2(h2[2*j+1],cv.u[1],yb);
            }
            float y=LOF(ya)+HIF(ya)+LOF(yb)+HIF(yb);
            int l=l0+i, pos;
            if(k==0) pos=l;
            else if(k==1){ pos=hh*WW+wc; hh++; if(hh==HH){hh=0;wc++;} }
            else pos=LL-1-l;
            yout[(size_t)pos*DI]=y;
        }
    } else {
        float rn[NS],h[NS];
#pragma unroll
        for(int n=0;n<NS;n++){ rn[n]=__expf(ar[n]-a0); h[n]=g_hin[seg][n][chain]; }
        for(int i=0;i<LSEG;i++){
            float2 ed=pre[(size_t)(l0+i)*DI];
            float lg=__log2f(ed.x), du=ed.y, y=0.f;
#pragma unroll
            for(int n=0;n<NS;n++){
                h[n]=exp2f(lg*rn[n])*h[n]+du*sb[i*32+n];
                y+=h[n]*sb[i*32+16+n];
            }
            int l=l0+i,pos;
            if(k==0)pos=l;
            else if(k==1){pos=hh*WW+wc;hh++;if(hh==HH){hh=0;wc++;}}
            else pos=LL-1-l;
            yout[(size_t)pos*DI]=y;
        }
    }
}

/* ------------- merge + D-term + gating + out_proj (vectorized) ------------- */
__global__ __launch_bounds__(256) void k_out(const float* __restrict__ ow, const float* __restrict__ Ds,
                                             float* __restrict__ out)
{
    __shared__ float yz[16*DI];
    __shared__ float dsum_s[DI];
    int tid=threadIdx.x;
    int tb=blockIdx.x*16;
    size_t base4=(size_t)tb*DI/4;
    if (tid < DI) dsum_s[tid]=Ds[tid]+Ds[DI+tid]+Ds[2*DI+tid];
    __syncthreads();
    {
        const float4* y0=reinterpret_cast<const float4*>(g_ys[0])+base4;
        const float4* y1=reinterpret_cast<const float4*>(g_ys[1])+base4;
        const float4* y2=reinterpret_cast<const float4*>(g_ys[2])+base4;
        const float4* xc=reinterpret_cast<const float4*>(g_xch)+base4;
        const float4* zz=reinterpret_cast<const float4*>(g_z)+base4;
#pragma unroll
        for(int it=0; it<3; it++){
            int i4 = tid + it*256;
            if (i4 < 16*DI/4){
                int dd4=(i4*4)%DI;
                float4 a=y0[i4], b=y1[i4], c=y2[i4], x=xc[i4], z=zz[i4];
                float4 ds=*reinterpret_cast<const float4*>(&dsum_s[dd4]);
                float4 v;
                v.x=(a.x+b.x+c.x+ds.x*x.x)*z.x;
                v.y=(a.y+b.y+c.y+ds.y*x.y)*z.y;
                v.z=(a.z+b.z+c.z+ds.z*x.z)*z.z;
                v.w=(a.w+b.w+c.w+ds.w*x.w)*z.w;
                *reinterpret_cast<float4*>(&yz[i4*4])=v;
            }
        }
    }
    __syncthreads();
    if(tid<192){
        int j = tid % DM;
        int t0 = (tid >= DM) ? 8 : 0;
        u64 acc[8];
#pragma unroll
        for(int t=0;t<8;t++) acc[t]=0ull;
        const float4* w4=reinterpret_cast<const float4*>(ow+(size_t)j*DI);
        for(int d4=0;d4<DI/4;d4++){
            F4U wv; wv.f=w4[d4];
#pragma unroll
            for(int t=0;t<8;t++){
                F4U xv; xv.f=*reinterpret_cast<const float4*>(&yz[(t0+t)*DI+d4*4]);
                acc[t]=fma2(wv.u[0],xv.u[0],acc[t]);
                acc[t]=fma2(wv.u[1],xv.u[1],acc[t]);
            }
        }
#pragma unroll
        for(int t=0;t<8;t++) out[(size_t)(tb+t0+t)*DM+j]=LOF(acc[t])+HIF(acc[t]);
    }
}

/* ---------------- launcher ---------------- */
extern "C" void kernel_launch(void* const* d_in, const int* in_sizes, int n_in,
                              void* d_out, int out_size)
{
    const float* x    = (const float*)d_in[0];
    const float* inw  = (const float*)d_in[2];
    const float* cw   = (const float*)d_in[3];
    const float* cb   = (const float*)d_in[4];
    const float* xw   = (const float*)d_in[5];
    const float* dtw  = (const float*)d_in[6];
    const float* dtb  = (const float*)d_in[7];
    const float* alog = (const float*)d_in[8];
    const float* Ds   = (const float*)d_in[9];
    const float* ow   = (const float*)d_in[10];
    float* out = (float*)d_out;

    k_inproj<<<BB*LL/16, 384>>>(x, inw);
    k_mid   <<<dim3(LL/TT, BB), 256>>>(cw, cb, xw, dtw, dtb, alog);
    k_scan1 <<<dim3(SS, BB*KK), DI>>>(alog);
    k_comb  <<<CH*NS/256, 256>>>(alog);
    k_scan2 <<<dim3(SS, BB*KK), DI>>>(alog);
    k_out   <<<BB*LL/16, 256>>>(ow, Ds, out);
}

// round 10
// speedup vs baseline: 1.3855x; 1.0528x over previous
#include <cuda_runtime.h>
#include <math.h>

#define BB 4
#define HH 48
#define WW 48
#define LL (HH*WW)      /* 2304 */
#define DM 96
#define DI 192
#define NS 16
#define RR 6
#define KK 3
#define XD 32           /* row: [B0..B15, C0..C15] */
#define CH (BB*KK*DI)   /* 2304 chains */
#define SS 64           /* scan segments */
#define LSEG (LL/SS)    /* 36 */
#define TT 32           /* spatial tokens per k_mid block */

typedef unsigned long long u64;
union F2U { float2 f; u64 u; };
union F4U { float4 f; u64 u[2]; };

__device__ __forceinline__ u64 F2P(float x, float y){ F2U t; t.f=make_float2(x,y); return t.u; }
__device__ __forceinline__ float LOF(u64 v){ F2U t; t.u=v; return t.f.x; }
__device__ __forceinline__ float HIF(u64 v){ F2U t; t.u=v; return t.f.y; }
__device__ __forceinline__ u64 fma2(u64 a,u64 b,u64 c){ u64 d; asm("fma.rn.f32x2 %0,%1,%2,%3;":"=l"(d):"l"(a),"l"(b),"l"(c)); return d; }
__device__ __forceinline__ u64 mul2(u64 a,u64 b){ u64 d; asm("mul.rn.f32x2 %0,%1,%2;":"=l"(d):"l"(a),"l"(b)); return d; }

/* ---------------- scratch ---------------- */
__device__ float  g_xcraw[BB*LL*DI];
__device__ float  g_z    [BB*LL*DI];
__device__ float  g_xch  [BB*LL*DI];
__device__ float  g_xdbl [BB*KK*LL*XD];
__device__ float2 g_pre  [(size_t)BB*KK*LL*DI];   /* {e1, dt*u}  [bk][l][d] */
__device__ float  g_segq [SS][NS][CH];
__device__ float  g_segp [SS][CH];
__device__ float  g_hin  [SS][NS][CH];
__device__ float  g_ys   [KK][BB*LL*DI];

__device__ __forceinline__ float fsilu(float v){ return v / (1.f + __expf(-v)); }

/* ------------- in_proj ------------- */
__global__ void k_inproj(const float* __restrict__ x, const float* __restrict__ w)
{
    __shared__ float xt[16*DM];
    int tb = blockIdx.x * 16;
    for (int i=threadIdx.x;i<16*DM;i+=blockDim.x) xt[i]=x[(size_t)tb*DM+i];
    __syncthreads();
    int j = threadIdx.x;
    u64 acc[16];
#pragma unroll
    for(int t=0;t<16;t++) acc[t]=0ull;
    const float4* w4 = reinterpret_cast<const float4*>(w + j*DM);
#pragma unroll
    for(int c4=0;c4<DM/4;c4++){
        F4U wv; wv.f = w4[c4];
#pragma unroll
        for(int t=0;t<16;t++){
            F4U xv; xv.f = *reinterpret_cast<const float4*>(&xt[t*DM+c4*4]);
            acc[t]=fma2(wv.u[0],xv.u[0],acc[t]);
            acc[t]=fma2(wv.u[1],xv.u[1],acc[t]);
        }
    }
    if(j<DI){
#pragma unroll
        for(int t=0;t<16;t++) g_xcraw[(size_t)(tb+t)*DI+j]=LOF(acc[t])+HIF(acc[t]);
    } else {
        int jz=j-DI;
#pragma unroll
        for(int t=0;t<16;t++) g_z[(size_t)(tb+t)*DI+jz]=fsilu(LOF(acc[t])+HIF(acc[t]));
    }
}

/* ------------- fused conv + x_proj + dt_proj + delta ------------- */
__global__ __launch_bounds__(256) void k_mid(
    const float* __restrict__ cw, const float* __restrict__ cb,
    const float* __restrict__ xw,
    const float* __restrict__ dtw_g, const float* __restrict__ dtb_g,
    const float* __restrict__ alog)
{
    __shared__ float sxc[TT*DI];
    __shared__ float stage[KK*TT][40];
    int b  = blockIdx.y;
    int l0 = blockIdx.x * TT;
    int tid = threadIdx.x;

    if (tid < DI){
        int d = tid;
        float wt[9];
#pragma unroll
        for(int i=0;i<9;i++) wt[i]=cw[d*9+i];
        float bias=cb[d];
        const float* base = g_xcraw + (size_t)b*LL*DI + d;
        float* xo = g_xch + ((size_t)b*LL + l0)*DI + d;
#pragma unroll 4
        for(int t=0;t<TT;t++){
            int l=l0+t, h=l/WW, w0=l%WW;
            float s=bias;
#pragma unroll
            for(int kh=0;kh<3;kh++){
                int h2=h+kh-1;
                if((unsigned)h2>=HH) continue;
#pragma unroll
                for(int kw=0;kw<3;kw++){
                    int w2=w0+kw-1;
                    if((unsigned)w2>=WW) continue;
                    s += base[(size_t)(h2*WW+w2)*DI]*wt[kh*3+kw];
                }
            }
            float v=fsilu(s);
            sxc[t*DI+d]=v;
            xo[(size_t)t*DI]=v;
        }
    }
    __syncthreads();

    if (tid < 228){
        int j = tid % 114;
        int t0 = (tid >= 114) ? 16 : 0;
        int k = j/38, c = j%38;
        u64 acc[16];
#pragma unroll
        for(int t=0;t<16;t++) acc[t]=0ull;
        const float4* w4 = reinterpret_cast<const float4*>(xw + (size_t)(k*38+c)*DI);
        for(int d4=0; d4<DI/4; d4++){
            F4U wv; wv.f=w4[d4];
#pragma unroll
            for(int t=0;t<16;t++){
                F4U xv; xv.f=*reinterpret_cast<const float4*>(&sxc[(t0+t)*DI+d4*4]);
                acc[t]=fma2(wv.u[0],xv.u[0],acc[t]);
                acc[t]=fma2(wv.u[1],xv.u[1],acc[t]);
            }
        }
        int slot = (c<RR)? c : (c<RR+NS ? 8+(c-RR) : 24+(c-RR-NS));
#pragma unroll
        for(int t=0;t<16;t++) stage[k*TT+t0+t][slot]=LOF(acc[t])+HIF(acc[t]);
    }
    __syncthreads();

    if (tid < DI){
        int d = tid;
#pragma unroll
        for(int k=0;k<KK;k++){
            float dtw[RR];
#pragma unroll
            for(int r=0;r<RR;r++) dtw[r]=dtw_g[(size_t)(k*DI+d)*RR+r];
            float bias=dtb_g[k*DI+d];
            float A0 = -__expf(alog[(size_t)(k*DI+d)*NS]);
            float2* pb = g_pre + ((size_t)(b*KK+k)*LL)*DI + d;
#pragma unroll 4
            for(int t=0;t<TT;t++){
                int lsp=l0+t;
                int p = (k==0)? lsp : (k==1 ? (lsp%WW)*HH + lsp/WW : LL-1-lsp);
                float s=bias;
#pragma unroll
                for(int r=0;r<RR;r++) s += dtw[r]*stage[k*TT+t][r];
                float dt = fmaxf(s,0.f) + __logf(1.f + __expf(-fabsf(s)));
                float e1 = __expf(dt * A0);
                pb[(size_t)p*DI] = make_float2(e1, dt*sxc[t*DI+d]);
            }
        }
    }

    for(int i=tid; i<KK*TT*XD; i+=256){
        int row=i/XD, j=i%XD;
        int k=row/TT, t=row%TT;
        int lsp=l0+t;
        int p = (k==0)? lsp : (k==1 ? (lsp%WW)*HH + lsp/WW : LL-1-lsp);
        g_xdbl[((size_t)(b*KK+k)*LL+p)*XD + j] = stage[row][8+j];
    }
}

/* tree powers: a[j] = (e1^(2j+1), e1^(2j+2)) */
__device__ __forceinline__ void tree_pow(float e1, u64 a[8]){
    float e2=e1*e1, e4=e2*e2, e8=e4*e4;
    u64 e2p=F2P(e2,e2), e4p=F2P(e4,e4), e8p=F2P(e8,e8);
    a[0]=F2P(e1,e2);
    a[1]=mul2(a[0],e2p);
    a[2]=mul2(a[0],e4p);
    a[3]=mul2(a[1],e4p);
    a[4]=mul2(a[0],e8p);
    a[5]=mul2(a[1],e8p);
    a[6]=mul2(a[2],e8p);
    a[7]=mul2(a[3],e8p);
}

/* one unit-path scan step (states packed in h2[8]) */
__device__ __forceinline__ void scan_step1(float2 ed, const float* sbrow, u64 h2[8]){
    u64 du2=F2P(ed.y,ed.y);
    u64 a[8]; tree_pow(ed.x, a);
    const F4U* bp=reinterpret_cast<const F4U*>(sbrow);
#pragma unroll
    for(int j=0;j<4;j++){
        F4U bv=bp[j];
        h2[2*j]  = fma2(a[2*j],  h2[2*j],  mul2(du2,bv.u[0]));
        h2[2*j+1]= fma2(a[2*j+1],h2[2*j+1],mul2(du2,bv.u[1]));
    }
}

/* ------------- scan pass 1: segment summaries, h0=0 (PF=2 prefetch) ------------- */
__global__ __launch_bounds__(DI, 6) void k_scan1(const float* __restrict__ alog)
{
    __shared__ float sb[LSEG*32];
    int seg = blockIdx.x, bk = blockIdx.y;
    int d = threadIdx.x;
    int chain = bk*DI + d;
    int k = bk % KK;
    int l0 = seg*LSEG;
    {
        const float4* src = reinterpret_cast<const float4*>(g_xdbl + ((size_t)bk*LL + l0)*XD);
        for(int i=threadIdx.x;i<LSEG*8;i+=blockDim.x)
            reinterpret_cast<float4*>(sb)[i]=src[i];
    }
    __syncthreads();

    const float* ar = alog + (size_t)(k*DI+d)*NS;
    float a0 = ar[0];
    bool unit=true;
#pragma unroll
    for(int n=0;n<NS;n++){
        float r=__expf(ar[n]-a0);
        unit = unit && (fabsf(r-(float)(n+1))<1e-3f);
    }
    bool wunit = __all_sync(0xffffffffu, unit);
    const float2* pre = g_pre + (size_t)bk*LL*DI + d;
    float pe=1.f;
    if(wunit){
        u64 h2[8];
#pragma unroll
        for(int j=0;j<8;j++) h2[j]=0ull;
        float2 c0=pre[(size_t)l0*DI], c1=pre[(size_t)(l0+1)*DI];
#pragma unroll
        for(int io=0;io<LSEG;io+=2){
            float2 n0=c0, n1=c1;
            if(io+2<LSEG){ n0=pre[(size_t)(l0+io+2)*DI]; n1=pre[(size_t)(l0+io+3)*DI]; }
            pe*=c0.x; scan_step1(c0, &sb[io*32], h2);
            pe*=c1.x; scan_step1(c1, &sb[(io+1)*32], h2);
            c0=n0; c1=n1;
        }
#pragma unroll
        for(int j=0;j<8;j++){
            g_segq[seg][2*j][chain]  =LOF(h2[j]);
            g_segq[seg][2*j+1][chain]=HIF(h2[j]);
        }
    } else {
        float rn[NS], h[NS];
#pragma unroll
        for(int n=0;n<NS;n++){ rn[n]=__expf(ar[n]-a0); h[n]=0.f; }
        for(int i=0;i<LSEG;i++){
            float2 ed=pre[(size_t)(l0+i)*DI];
            pe*=ed.x;
            float lg=__log2f(ed.x), du=ed.y;
#pragma unroll
            for(int n=0;n<NS;n++)
                h[n]=exp2f(lg*rn[n])*h[n] + du*sb[i*32+n];
        }
#pragma unroll
        for(int n=0;n<NS;n++) g_segq[seg][n][chain]=h[n];
    }
    g_segp[seg][chain]=pe;
}

/* ------------- combine: two-level parallel prefix (8 threads per chain-state) ------------- */
__global__ __launch_bounds__(256) void k_comb(const float* __restrict__ alog)
{
    int gt = blockIdx.x*256 + threadIdx.x;   /* CH*NS*8 threads */
    int t  = gt & 7;
    int cn = gt >> 3;
    int chain = cn % CH;
    int n  = cn / CH;
    int d = chain % DI, k = (chain / DI) % KK;
    const float* ar = alog + (size_t)(k*DI+d)*NS;
    float ratio = __expf(ar[n] - ar[0]);
    float rf = rintf(ratio);
    int   m  = (int)rf;
    bool exact = (fabsf(ratio-rf) < 1e-3f) && m >= 1 && m <= 31;
    int s0 = t*8;
    float A=1.f, Q=0.f;
    float Ap[8], Qp[8];
#pragma unroll
    for(int i=0;i<8;i++){
        Ap[i]=A; Qp[i]=Q;
        float pe = __ldg(&g_segp[s0+i][chain]);
        float q  = __ldg(&g_segq[s0+i][n][chain]);
        float a;
        if (exact){
            float pe2=pe*pe, pe4=pe2*pe2, pe8=pe4*pe4, pe16=pe8*pe8;
            a = (m&1)? pe : 1.f;
            if(m&2)  a*=pe2;
            if(m&4)  a*=pe4;
            if(m&8)  a*=pe8;
            if(m&16) a*=pe16;
        } else {
            a = exp2f(__log2f(pe)*ratio);
        }
        A = a*A;
        Q = a*Q + q;
    }
    /* inclusive compose-scan across the 8 lanes of this chain-state */
#pragma unroll
    for(int dlt=1; dlt<8; dlt<<=1){
        float Apv = __shfl_up_sync(0xffffffffu, A, dlt, 8);
        float Qpv = __shfl_up_sync(0xffffffffu, Q, dlt, 8);
        if (t >= dlt){ Q = A*Qpv + Q; A = A*Apv; }
    }
    float hin = __shfl_up_sync(0xffffffffu, Q, 1, 8);
    if (t == 0) hin = 0.f;
#pragma unroll
    for(int i=0;i<8;i++)
        g_hin[s0+i][n][chain] = Ap[i]*hin + Qp[i];
}

/* ------------- scan pass 2: rescan with h_init, emit y (PF=2 prefetch) ------------- */
__global__ __launch_bounds__(DI, 6) void k_scan2(const float* __restrict__ alog)
{
    __shared__ float sb[LSEG*32];
    int seg=blockIdx.x, bk=blockIdx.y;
    int d=threadIdx.x;
    int chain=bk*DI+d;
    int k=bk%KK, b=bk/KK;
    int l0=seg*LSEG;
    {
        const float4* src = reinterpret_cast<const float4*>(g_xdbl + ((size_t)bk*LL + l0)*XD);
        for(int i=threadIdx.x;i<LSEG*8;i+=blockDim.x)
            reinterpret_cast<float4*>(sb)[i]=src[i];
    }
    __syncthreads();
    const float* ar=alog+(size_t)(k*DI+d)*NS;
    float a0=ar[0];
    bool unit=true;
#pragma unroll
    for(int n=0;n<NS;n++){ float r=__expf(ar[n]-a0); unit=unit&&(fabsf(r-(float)(n+1))<1e-3f); }
    bool wunit=__all_sync(0xffffffffu,unit);
    const float2* pre=g_pre+(size_t)bk*LL*DI+d;
    float* yout=g_ys[k]+(size_t)b*LL*DI+d;
    int hh=l0%HH, wc=l0/HH;
    if(wunit){
        u64 h2[8];
#pragma unroll
        for(int j=0;j<8;j++) h2[j]=F2P(g_hin[seg][2*j][chain], g_hin[seg][2*j+1][chain]);
        float2 c0=pre[(size_t)l0*DI], c1=pre[(size_t)(l0+1)*DI];
        for(int io=0;io<LSEG;io+=2){
            float2 n0=c0, n1=c1;
            if(io+2<LSEG){ n0=pre[(size_t)(l0+io+2)*DI]; n1=pre[(size_t)(l0+io+3)*DI]; }
#pragma unroll
            for(int half=0; half<2; half++){
                float2 ed = half? c1 : c0;
                int i = io + half;
                u64 du2=F2P(ed.y,ed.y);
                u64 a[8]; tree_pow(ed.x, a);
                const F4U* bp=reinterpret_cast<const F4U*>(&sb[i*32]);
                const F4U* cp=reinterpret_cast<const F4U*>(&sb[i*32+16]);
                u64 ya=0ull, yb=0ull;
#pragma unroll
                for(int j=0;j<4;j++){
                    F4U bv=bp[j]; F4U cv=cp[j];
                    h2[2*j]  =fma2(a[2*j],  h2[2*j],  mul2(du2,bv.u[0])); ya=fma2(h2[2*j],  cv.u[0],ya);
                    h2[2*j+1]=fma2(a[2*j+1],h2[2*j+1],mul2(du2,bv.u[1])); yb=fma2(h2[2*j+1],cv.u[1],yb);
                }
                float y=LOF(ya)+HIF(ya)+LOF(yb)+HIF(yb);
                int l=l0+i, pos;
                if(k==0) pos=l;
                else if(k==1){ pos=hh*WW+wc; hh++; if(hh==HH){hh=0;wc++;} }
                else pos=LL-1-l;
                yout[(size_t)pos*DI]=y;
            }
            c0=n0; c1=n1;
        }
    } else {
        float rn[NS],h[NS];
#pragma unroll
        for(int n=0;n<NS;n++){ rn[n]=__expf(ar[n]-a0); h[n]=g_hin[seg][n][chain]; }
        for(int i=0;i<LSEG;i++){
            float2 ed=pre[(size_t)(l0+i)*DI];
            float lg=__log2f(ed.x), du=ed.y, y=0.f;
#pragma unroll
            for(int n=0;n<NS;n++){
                h[n]=exp2f(lg*rn[n])*h[n]+du*sb[i*32+n];
                y+=h[n]*sb[i*32+16+n];
            }
            int l=l0+i,pos;
            if(k==0)pos=l;
            else if(k==1){pos=hh*WW+wc;hh++;if(hh==HH){hh=0;wc++;}}
            else pos=LL-1-l;
            yout[(size_t)pos*DI]=y;
        }
    }
}

/* ------------- merge (vectorized) + D-term + gating + out_proj (r7 GEMM) ------------- */
__global__ __launch_bounds__(128) void k_out(const float* __restrict__ ow, const float* __restrict__ Ds,
                                             float* __restrict__ out)
{
    __shared__ float yz[16*DI];
    __shared__ float dsum_s[DI];
    int tid=threadIdx.x;
    int tb=blockIdx.x*16;
    size_t base4=(size_t)tb*DI/4;
    for(int i=tid;i<DI;i+=128) dsum_s[i]=Ds[i]+Ds[DI+i]+Ds[2*DI+i];
    __syncthreads();
    {
        const float4* y0=reinterpret_cast<const float4*>(g_ys[0])+base4;
        const float4* y1=reinterpret_cast<const float4*>(g_ys[1])+base4;
        const float4* y2=reinterpret_cast<const float4*>(g_ys[2])+base4;
        const float4* xc=reinterpret_cast<const float4*>(g_xch)+base4;
        const float4* zz=reinterpret_cast<const float4*>(g_z)+base4;
#pragma unroll
        for(int it=0; it<6; it++){
            int i4 = tid + it*128;
            int dd4=(i4*4)%DI;
            float4 a=y0[i4], b=y1[i4], c=y2[i4], x=xc[i4], z=zz[i4];
            float4 ds=*reinterpret_cast<const float4*>(&dsum_s[dd4]);
            float4 v;
            v.x=(a.x+b.x+c.x+ds.x*x.x)*z.x;
            v.y=(a.y+b.y+c.y+ds.y*x.y)*z.y;
            v.z=(a.z+b.z+c.z+ds.z*x.z)*z.z;
            v.w=(a.w+b.w+c.w+ds.w*x.w)*z.w;
            *reinterpret_cast<float4*>(&yz[i4*4])=v;
        }
    }
    __syncthreads();
    int j=tid;
    if(j<DM){
        u64 acc[16];
#pragma unroll
        for(int t=0;t<16;t++) acc[t]=0ull;
        const float4* w4=reinterpret_cast<const float4*>(ow+(size_t)j*DI);
        for(int d4=0;d4<DI/4;d4++){
            F4U wv; wv.f=w4[d4];
#pragma unroll
            for(int t=0;t<16;t++){
                F4U xv; xv.f=*reinterpret_cast<const float4*>(&yz[t*DI+d4*4]);
                acc[t]=fma2(wv.u[0],xv.u[0],acc[t]);
                acc[t]=fma2(wv.u[1],xv.u[1],acc[t]);
            }
        }
#pragma unroll
        for(int t=0;t<16;t++) out[(size_t)(tb+t)*DM+j]=LOF(acc[t])+HIF(acc[t]);
    }
}

/* ---------------- launcher ---------------- */
extern "C" void kernel_launch(void* const* d_in, const int* in_sizes, int n_in,
                              void* d_out, int out_size)
{
    const float* x    = (const float*)d_in[0];
    const float* inw  = (const float*)d_in[2];
    const float* cw   = (const float*)d_in[3];
    const float* cb   = (const float*)d_in[4];
    const float* xw   = (const float*)d_in[5];
    const float* dtw  = (const float*)d_in[6];
    const float* dtb  = (const float*)d_in[7];
    const float* alog = (const float*)d_in[8];
    const float* Ds   = (const float*)d_in[9];
    const float* ow   = (const float*)d_in[10];
    float* out = (float*)d_out;

    k_inproj<<<BB*LL/16, 384>>>(x, inw);
    k_mid   <<<dim3(LL/TT, BB), 256>>>(cw, cb, xw, dtw, dtb, alog);
    k_scan1 <<<dim3(SS, BB*KK), DI>>>(alog);
    k_comb  <<<CH*NS*8/256, 256>>>(alog);
    k_scan2 <<<dim3(SS, BB*KK), DI>>>(alog);
    k_out   <<<BB*LL/16, 128>>>(ow, Ds, out);
}

// round 11
// speedup vs baseline: 1.3860x; 1.0003x over previous
#include <cuda_runtime.h>
#include <math.h>

#define BB 4
#define HH 48
#define WW 48
#define LL (HH*WW)      /* 2304 */
#define DM 96
#define DI 192
#define NS 16
#define RR 6
#define KK 3
#define XD 32           /* row: [B0..B15, C0..C15] */
#define CH (BB*KK*DI)   /* 2304 chains */
#define SS 64           /* scan segments */
#define LSEG (LL/SS)    /* 36 */
#define TT 32           /* spatial tokens per k_mid block */

typedef unsigned long long u64;
union F2U { float2 f; u64 u; };
union F4U { float4 f; u64 u[2]; };

__device__ __forceinline__ u64 F2P(float x, float y){ F2U t; t.f=make_float2(x,y); return t.u; }
__device__ __forceinline__ float LOF(u64 v){ F2U t; t.u=v; return t.f.x; }
__device__ __forceinline__ float HIF(u64 v){ F2U t; t.u=v; return t.f.y; }
__device__ __forceinline__ u64 fma2(u64 a,u64 b,u64 c){ u64 d; asm("fma.rn.f32x2 %0,%1,%2,%3;":"=l"(d):"l"(a),"l"(b),"l"(c)); return d; }
__device__ __forceinline__ u64 mul2(u64 a,u64 b){ u64 d; asm("mul.rn.f32x2 %0,%1,%2;":"=l"(d):"l"(a),"l"(b)); return d; }

/* ---------------- scratch ---------------- */
__device__ float  g_xcraw[BB*LL*DI];
__device__ float  g_z    [BB*LL*DI];
__device__ float  g_xch  [BB*LL*DI];
__device__ float  g_xdbl [BB*KK*LL*XD];
__device__ float2 g_pre  [(size_t)BB*KK*LL*DI];   /* {e1, dt*u}  [bk][l][d] */
__device__ float  g_segq [SS][NS][CH];
__device__ float  g_segp [SS][CH];
__device__ float  g_hin  [SS][NS][CH];
__device__ float  g_ys   [KK][BB*LL*DI];

__device__ __forceinline__ float fsilu(float v){ return v / (1.f + __expf(-v)); }

/* ------------- in_proj ------------- */
__global__ void k_inproj(const float* __restrict__ x, const float* __restrict__ w)
{
    __shared__ float xt[16*DM];
    int tb = blockIdx.x * 16;
    for (int i=threadIdx.x;i<16*DM;i+=blockDim.x) xt[i]=x[(size_t)tb*DM+i];
    __syncthreads();
    int j = threadIdx.x;
    u64 acc[16];
#pragma unroll
    for(int t=0;t<16;t++) acc[t]=0ull;
    const float4* w4 = reinterpret_cast<const float4*>(w + j*DM);
#pragma unroll
    for(int c4=0;c4<DM/4;c4++){
        F4U wv; wv.f = w4[c4];
#pragma unroll
        for(int t=0;t<16;t++){
            F4U xv; xv.f = *reinterpret_cast<const float4*>(&xt[t*DM+c4*4]);
            acc[t]=fma2(wv.u[0],xv.u[0],acc[t]);
            acc[t]=fma2(wv.u[1],xv.u[1],acc[t]);
        }
    }
    if(j<DI){
#pragma unroll
        for(int t=0;t<16;t++) g_xcraw[(size_t)(tb+t)*DI+j]=LOF(acc[t])+HIF(acc[t]);
    } else {
        int jz=j-DI;
#pragma unroll
        for(int t=0;t<16;t++) g_z[(size_t)(tb+t)*DI+jz]=fsilu(LOF(acc[t])+HIF(acc[t]));
    }
}

/* ------------- fused conv + x_proj + dt_proj + delta ------------- */
__global__ __launch_bounds__(256) void k_mid(
    const float* __restrict__ cw, const float* __restrict__ cb,
    const float* __restrict__ xw,
    const float* __restrict__ dtw_g, const float* __restrict__ dtb_g,
    const float* __restrict__ alog)
{
    __shared__ float sxc[TT*DI];
    __shared__ float stage[KK*TT][40];
    int b  = blockIdx.y;
    int l0 = blockIdx.x * TT;
    int tid = threadIdx.x;

    if (tid < DI){
        int d = tid;
        float wt[9];
#pragma unroll
        for(int i=0;i<9;i++) wt[i]=cw[d*9+i];
        float bias=cb[d];
        const float* base = g_xcraw + (size_t)b*LL*DI + d;
        float* xo = g_xch + ((size_t)b*LL + l0)*DI + d;
#pragma unroll 4
        for(int t=0;t<TT;t++){
            int l=l0+t, h=l/WW, w0=l%WW;
            float s=bias;
#pragma unroll
            for(int kh=0;kh<3;kh++){
                int h2=h+kh-1;
                if((unsigned)h2>=HH) continue;
#pragma unroll
                for(int kw=0;kw<3;kw++){
                    int w2=w0+kw-1;
                    if((unsigned)w2>=WW) continue;
                    s += base[(size_t)(h2*WW+w2)*DI]*wt[kh*3+kw];
                }
            }
            float v=fsilu(s);
            sxc[t*DI+d]=v;
            xo[(size_t)t*DI]=v;
        }
    }
    __syncthreads();

    if (tid < 228){
        int j = tid % 114;
        int t0 = (tid >= 114) ? 16 : 0;
        int k = j/38, c = j%38;
        u64 acc[16];
#pragma unroll
        for(int t=0;t<16;t++) acc[t]=0ull;
        const float4* w4 = reinterpret_cast<const float4*>(xw + (size_t)(k*38+c)*DI);
        for(int d4=0; d4<DI/4; d4++){
            F4U wv; wv.f=w4[d4];
#pragma unroll
            for(int t=0;t<16;t++){
                F4U xv; xv.f=*reinterpret_cast<const float4*>(&sxc[(t0+t)*DI+d4*4]);
                acc[t]=fma2(wv.u[0],xv.u[0],acc[t]);
                acc[t]=fma2(wv.u[1],xv.u[1],acc[t]);
            }
        }
        int slot = (c<RR)? c : (c<RR+NS ? 8+(c-RR) : 24+(c-RR-NS));
#pragma unroll
        for(int t=0;t<16;t++) stage[k*TT+t0+t][slot]=LOF(acc[t])+HIF(acc[t]);
    }
    __syncthreads();

    if (tid < DI){
        int d = tid;
#pragma unroll
        for(int k=0;k<KK;k++){
            float dtw[RR];
#pragma unroll
            for(int r=0;r<RR;r++) dtw[r]=dtw_g[(size_t)(k*DI+d)*RR+r];
            float bias=dtb_g[k*DI+d];
            float A0 = -__expf(alog[(size_t)(k*DI+d)*NS]);
            float2* pb = g_pre + ((size_t)(b*KK+k)*LL)*DI + d;
#pragma unroll 4
            for(int t=0;t<TT;t++){
                int lsp=l0+t;
                int p = (k==0)? lsp : (k==1 ? (lsp%WW)*HH + lsp/WW : LL-1-lsp);
                float s=bias;
#pragma unroll
                for(int r=0;r<RR;r++) s += dtw[r]*stage[k*TT+t][r];
                float dt = fmaxf(s,0.f) + __logf(1.f + __expf(-fabsf(s)));
                float e1 = __expf(dt * A0);
                pb[(size_t)p*DI] = make_float2(e1, dt*sxc[t*DI+d]);
            }
        }
    }

    for(int i=tid; i<KK*TT*XD; i+=256){
        int row=i/XD, j=i%XD;
        int k=row/TT, t=row%TT;
        int lsp=l0+t;
        int p = (k==0)? lsp : (k==1 ? (lsp%WW)*HH + lsp/WW : LL-1-lsp);
        g_xdbl[((size_t)(b*KK+k)*LL+p)*XD + j] = stage[row][8+j];
    }
}

/* tree powers: a[j] = (e1^(2j+1), e1^(2j+2)) */
__device__ __forceinline__ void tree_pow(float e1, u64 a[8]){
    float e2=e1*e1, e4=e2*e2, e8=e4*e4;
    u64 e2p=F2P(e2,e2), e4p=F2P(e4,e4), e8p=F2P(e8,e8);
    a[0]=F2P(e1,e2);
    a[1]=mul2(a[0],e2p);
    a[2]=mul2(a[0],e4p);
    a[3]=mul2(a[1],e4p);
    a[4]=mul2(a[0],e8p);
    a[5]=mul2(a[1],e8p);
    a[6]=mul2(a[2],e8p);
    a[7]=mul2(a[3],e8p);
}

/* one unit-path scan step (states packed in h2[8]) */
__device__ __forceinline__ void scan_step1(float2 ed, const float* sbrow, u64 h2[8]){
    u64 du2=F2P(ed.y,ed.y);
    u64 a[8]; tree_pow(ed.x, a);
    const F4U* bp=reinterpret_cast<const F4U*>(sbrow);
#pragma unroll
    for(int j=0;j<4;j++){
        F4U bv=bp[j];
        h2[2*j]  = fma2(a[2*j],  h2[2*j],  mul2(du2,bv.u[0]));
        h2[2*j+1]= fma2(a[2*j+1],h2[2*j+1],mul2(du2,bv.u[1]));
    }
}

/* ------------- scan pass 1: segment summaries, h0=0 (PF=2 prefetch) ------------- */
__global__ __launch_bounds__(DI, 6) void k_scan1(const float* __restrict__ alog)
{
    __shared__ float sb[LSEG*32];
    int seg = blockIdx.x, bk = blockIdx.y;
    int d = threadIdx.x;
    int chain = bk*DI + d;
    int k = bk % KK;
    int l0 = seg*LSEG;
    {
        const float4* src = reinterpret_cast<const float4*>(g_xdbl + ((size_t)bk*LL + l0)*XD);
        for(int i=threadIdx.x;i<LSEG*8;i+=blockDim.x)
            reinterpret_cast<float4*>(sb)[i]=src[i];
    }
    __syncthreads();

    const float* ar = alog + (size_t)(k*DI+d)*NS;
    float a0 = ar[0];
    bool unit=true;
#pragma unroll
    for(int n=0;n<NS;n++){
        float r=__expf(ar[n]-a0);
        unit = unit && (fabsf(r-(float)(n+1))<1e-3f);
    }
    bool wunit = __all_sync(0xffffffffu, unit);
    const float2* pre = g_pre + (size_t)bk*LL*DI + d;
    float pe=1.f;
    if(wunit){
        u64 h2[8];
#pragma unroll
        for(int j=0;j<8;j++) h2[j]=0ull;
        float2 c0=pre[(size_t)l0*DI], c1=pre[(size_t)(l0+1)*DI];
#pragma unroll
        for(int io=0;io<LSEG;io+=2){
            float2 n0=c0, n1=c1;
            if(io+2<LSEG){ n0=pre[(size_t)(l0+io+2)*DI]; n1=pre[(size_t)(l0+io+3)*DI]; }
            pe*=c0.x; scan_step1(c0, &sb[io*32], h2);
            pe*=c1.x; scan_step1(c1, &sb[(io+1)*32], h2);
            c0=n0; c1=n1;
        }
#pragma unroll
        for(int j=0;j<8;j++){
            g_segq[seg][2*j][chain]  =LOF(h2[j]);
            g_segq[seg][2*j+1][chain]=HIF(h2[j]);
        }
    } else {
        float rn[NS], h[NS];
#pragma unroll
        for(int n=0;n<NS;n++){ rn[n]=__expf(ar[n]-a0); h[n]=0.f; }
        for(int i=0;i<LSEG;i++){
            float2 ed=pre[(size_t)(l0+i)*DI];
            pe*=ed.x;
            float lg=__log2f(ed.x), du=ed.y;
#pragma unroll
            for(int n=0;n<NS;n++)
                h[n]=exp2f(lg*rn[n])*h[n] + du*sb[i*32+n];
        }
#pragma unroll
        for(int n=0;n<NS;n++) g_segq[seg][n][chain]=h[n];
    }
    g_segp[seg][chain]=pe;
}

/* ------------- combine: smem-staged coalesced two-level prefix ------------- */
__global__ __launch_bounds__(256) void k_comb(const float* __restrict__ alog)
{
    __shared__ float sp[32][65];   /* [c][s] segment decay products */
    __shared__ float sq[32][65];   /* [c][s] segment q; reused for hin output */
    int n  = blockIdx.x / (CH/32);         /* 72 blocks per state n */
    int c0 = (blockIdx.x % (CH/32)) * 32;
    int tid = threadIdx.x;

    for(int i=tid;i<SS*32;i+=256){ int s=i>>5, c=i&31; sp[c][s]=g_segp[s][c0+c]; }
    for(int i=tid;i<SS*32;i+=256){ int s=i>>5, c=i&31; sq[c][s]=g_segq[s][n][c0+c]; }
    __syncthreads();

    int t   = tid & 7;
    int cidx= tid >> 3;
    int chain = c0 + cidx;
    int d = chain % DI, k = (chain / DI) % KK;
    const float* ar = alog + (size_t)(k*DI+d)*NS;
    float ratio = __expf(ar[n] - ar[0]);
    float rf = rintf(ratio);
    int   m  = (int)rf;
    bool exact = (fabsf(ratio-rf) < 1e-3f) && m >= 1 && m <= 31;
    int s0 = t*8;
    float A=1.f, Q=0.f;
    float Ap[8], Qp[8];
#pragma unroll
    for(int i=0;i<8;i++){
        Ap[i]=A; Qp[i]=Q;
        float pe = sp[cidx][s0+i];
        float q  = sq[cidx][s0+i];
        float a;
        if (exact){
            float pe2=pe*pe, pe4=pe2*pe2, pe8=pe4*pe4, pe16=pe8*pe8;
            a = (m&1)? pe : 1.f;
            if(m&2)  a*=pe2;
            if(m&4)  a*=pe4;
            if(m&8)  a*=pe8;
            if(m&16) a*=pe16;
        } else {
            a = exp2f(__log2f(pe)*ratio);
        }
        A = a*A;
        Q = a*Q + q;
    }
    /* inclusive compose-scan across the 8 lanes of this chain-state */
#pragma unroll
    for(int dlt=1; dlt<8; dlt<<=1){
        float Apv = __shfl_up_sync(0xffffffffu, A, dlt, 8);
        float Qpv = __shfl_up_sync(0xffffffffu, Q, dlt, 8);
        if (t >= dlt){ Q = A*Qpv + Q; A = A*Apv; }
    }
    float hin = __shfl_up_sync(0xffffffffu, Q, 1, 8);
    if (t == 0) hin = 0.f;
#pragma unroll
    for(int i=0;i<8;i++)
        sq[cidx][s0+i] = Ap[i]*hin + Qp[i];   /* in-place: each (c,s) owned by one thread */
    __syncthreads();
    for(int i=tid;i<SS*32;i+=256){ int s=i>>5, c=i&31; g_hin[s][n][c0+c]=sq[c][s]; }
}

/* ------------- scan pass 2: rescan with h_init, emit y (PF=2 prefetch) ------------- */
__global__ __launch_bounds__(DI, 6) void k_scan2(const float* __restrict__ alog)
{
    __shared__ float sb[LSEG*32];
    int seg=blockIdx.x, bk=blockIdx.y;
    int d=threadIdx.x;
    int chain=bk*DI+d;
    int k=bk%KK, b=bk/KK;
    int l0=seg*LSEG;
    {
        const float4* src = reinterpret_cast<const float4*>(g_xdbl + ((size_t)bk*LL + l0)*XD);
        for(int i=threadIdx.x;i<LSEG*8;i+=blockDim.x)
            reinterpret_cast<float4*>(sb)[i]=src[i];
    }
    __syncthreads();
    const float* ar=alog+(size_t)(k*DI+d)*NS;
    float a0=ar[0];
    bool unit=true;
#pragma unroll
    for(int n=0;n<NS;n++){ float r=__expf(ar[n]-a0); unit=unit&&(fabsf(r-(float)(n+1))<1e-3f); }
    bool wunit=__all_sync(0xffffffffu,unit);
    const float2* pre=g_pre+(size_t)bk*LL*DI+d;
    float* yout=g_ys[k]+(size_t)b*LL*DI+d;
    int hh=l0%HH, wc=l0/HH;
    if(wunit){
        u64 h2[8];
#pragma unroll
        for(int j=0;j<8;j++) h2[j]=F2P(g_hin[seg][2*j][chain], g_hin[seg][2*j+1][chain]);
        float2 c0=pre[(size_t)l0*DI], c1=pre[(size_t)(l0+1)*DI];
        for(int io=0;io<LSEG;io+=2){
            float2 n0=c0, n1=c1;
            if(io+2<LSEG){ n0=pre[(size_t)(l0+io+2)*DI]; n1=pre[(size_t)(l0+io+3)*DI]; }
#pragma unroll
            for(int half=0; half<2; half++){
                float2 ed = half? c1 : c0;
                int i = io + half;
                u64 du2=F2P(ed.y,ed.y);
                u64 a[8]; tree_pow(ed.x, a);
                const F4U* bp=reinterpret_cast<const F4U*>(&sb[i*32]);
                const F4U* cp=reinterpret_cast<const F4U*>(&sb[i*32+16]);
                u64 ya=0ull, yb=0ull;
#pragma unroll
                for(int j=0;j<4;j++){
                    F4U bv=bp[j]; F4U cv=cp[j];
                    h2[2*j]  =fma2(a[2*j],  h2[2*j],  mul2(du2,bv.u[0])); ya=fma2(h2[2*j],  cv.u[0],ya);
                    h2[2*j+1]=fma2(a[2*j+1],h2[2*j+1],mul2(du2,bv.u[1])); yb=fma2(h2[2*j+1],cv.u[1],yb);
                }
                float y=LOF(ya)+HIF(ya)+LOF(yb)+HIF(yb);
                int l=l0+i, pos;
                if(k==0) pos=l;
                else if(k==1){ pos=hh*WW+wc; hh++; if(hh==HH){hh=0;wc++;} }
                else pos=LL-1-l;
                yout[(size_t)pos*DI]=y;
            }
            c0=n0; c1=n1;
        }
    } else {
        float rn[NS],h[NS];
#pragma unroll
        for(int n=0;n<NS;n++){ rn[n]=__expf(ar[n]-a0); h[n]=g_hin[seg][n][chain]; }
        for(int i=0;i<LSEG;i++){
            float2 ed=pre[(size_t)(l0+i)*DI];
            float lg=__log2f(ed.x), du=ed.y, y=0.f;
#pragma unroll
            for(int n=0;n<NS;n++){
                h[n]=exp2f(lg*rn[n])*h[n]+du*sb[i*32+n];
                y+=h[n]*sb[i*32+16+n];
            }
            int l=l0+i,pos;
            if(k==0)pos=l;
            else if(k==1){pos=hh*WW+wc;hh++;if(hh==HH){hh=0;wc++;}}
            else pos=LL-1-l;
            yout[(size_t)pos*DI]=y;
        }
    }
}

/* ------------- merge (vectorized) + D-term + gating + out_proj ------------- */
__global__ __launch_bounds__(128) void k_out(const float* __restrict__ ow, const float* __restrict__ Ds,
                                             float* __restrict__ out)
{
    __shared__ float yz[16*DI];
    __shared__ float dsum_s[DI];
    int tid=threadIdx.x;
    int tb=blockIdx.x*16;
    size_t base4=(size_t)tb*DI/4;
    for(int i=tid;i<DI;i+=128) dsum_s[i]=Ds[i]+Ds[DI+i]+Ds[2*DI+i];
    __syncthreads();
    {
        const float4* y0=reinterpret_cast<const float4*>(g_ys[0])+base4;
        const float4* y1=reinterpret_cast<const float4*>(g_ys[1])+base4;
        const float4* y2=reinterpret_cast<const float4*>(g_ys[2])+base4;
        const float4* xc=reinterpret_cast<const float4*>(g_xch)+base4;
        const float4* zz=reinterpret_cast<const float4*>(g_z)+base4;
#pragma unroll
        for(int it=0; it<6; it++){
            int i4 = tid + it*128;
            int dd4=(i4*4)%DI;
            float4 a=y0[i4], b=y1[i4], c=y2[i4], x=xc[i4], z=zz[i4];
            float4 ds=*reinterpret_cast<const float4*>(&dsum_s[dd4]);
            float4 v;
            v.x=(a.x+b.x+c.x+ds.x*x.x)*z.x;
            v.y=(a.y+b.y+c.y+ds.y*x.y)*z.y;
            v.z=(a.z+b.z+c.z+ds.z*x.z)*z.z;
            v.w=(a.w+b.w+c.w+ds.w*x.w)*z.w;
            *reinterpret_cast<float4*>(&yz[i4*4])=v;
        }
    }
    __syncthreads();
    int j=tid;
    if(j<DM){
        u64 acc[16];
#pragma unroll
        for(int t=0;t<16;t++) acc[t]=0ull;
        const float4* w4=reinterpret_cast<const float4*>(ow+(size_t)j*DI);
        for(int d4=0;d4<DI/4;d4++){
            F4U wv; wv.f=w4[d4];
#pragma unroll
            for(int t=0;t<16;t++){
                F4U xv; xv.f=*reinterpret_cast<const float4*>(&yz[t*DI+d4*4]);
                acc[t]=fma2(wv.u[0],xv.u[0],acc[t]);
                acc[t]=fma2(wv.u[1],xv.u[1],acc[t]);
            }
        }
#pragma unroll
        for(int t=0;t<16;t++) out[(size_t)(tb+t)*DM+j]=LOF(acc[t])+HIF(acc[t]);
    }
}

/* ---------------- launcher ---------------- */
extern "C" void kernel_launch(void* const* d_in, const int* in_sizes, int n_in,
                              void* d_out, int out_size)
{
    const float* x    = (const float*)d_in[0];
    const float* inw  = (const float*)d_in[2];
    const float* cw   = (const float*)d_in[3];
    const float* cb   = (const float*)d_in[4];
    const float* xw   = (const float*)d_in[5];
    const float* dtw  = (const float*)d_in[6];
    const float* dtb  = (const float*)d_in[7];
    const float* alog = (const float*)d_in[8];
    const float* Ds   = (const float*)d_in[9];
    const float* ow   = (const float*)d_in[10];
    float* out = (float*)d_out;

    k_inproj<<<BB*LL/16, 384>>>(x, inw);
    k_mid   <<<dim3(LL/TT, BB), 256>>>(cw, cb, xw, dtw, dtb, alog);
    k_scan1 <<<dim3(SS, BB*KK), DI>>>(alog);
    k_comb  <<<NS*(CH/32), 256>>>(alog);
    k_scan2 <<<dim3(SS, BB*KK), DI>>>(alog);
    k_out   <<<BB*LL/16, 128>>>(ow, Ds, out);
}

// round 12
// speedup vs baseline: 1.4009x; 1.0108x over previous
#include <cuda_runtime.h>
#include <math.h>

#define BB 4
#define HH 48
#define WW 48
#define LL (HH*WW)      /* 2304 */
#define DM 96
#define DI 192
#define NS 16
#define RR 6
#define KK 3
#define XD 32           /* row: [B0..B15, C0..C15] */
#define CH (BB*KK*DI)   /* 2304 chains */
#define SS 64           /* scan segments */
#define LSEG (LL/SS)    /* 36 */
#define TT 16           /* spatial tokens per k_mid block */

typedef unsigned long long u64;
union F2U { float2 f; u64 u; };
union F4U { float4 f; u64 u[2]; };

__device__ __forceinline__ u64 F2P(float x, float y){ F2U t; t.f=make_float2(x,y); return t.u; }
__device__ __forceinline__ float LOF(u64 v){ F2U t; t.u=v; return t.f.x; }
__device__ __forceinline__ float HIF(u64 v){ F2U t; t.u=v; return t.f.y; }
__device__ __forceinline__ u64 fma2(u64 a,u64 b,u64 c){ u64 d; asm("fma.rn.f32x2 %0,%1,%2,%3;":"=l"(d):"l"(a),"l"(b),"l"(c)); return d; }
__device__ __forceinline__ u64 mul2(u64 a,u64 b){ u64 d; asm("mul.rn.f32x2 %0,%1,%2;":"=l"(d):"l"(a),"l"(b)); return d; }

/* ---------------- scratch ---------------- */
__device__ float  g_xcraw[BB*LL*DI];
__device__ float  g_z    [BB*LL*DI];
__device__ float  g_xch  [BB*LL*DI];
__device__ float  g_xdbl [BB*KK*LL*XD];
__device__ float2 g_pre  [(size_t)BB*KK*LL*DI];   /* {e1, dt*u}  [bk][l][d] */
__device__ float  g_segq [SS][NS][CH];
__device__ float  g_segp [SS][CH];
__device__ float  g_hin  [SS][NS][CH];
__device__ float  g_ys   [KK][BB*LL*DI];

__device__ __forceinline__ float fsilu(float v){ return v / (1.f + __expf(-v)); }

/* ------------- in_proj ------------- */
__global__ void k_inproj(const float* __restrict__ x, const float* __restrict__ w)
{
    __shared__ float xt[16*DM];
    int tb = blockIdx.x * 16;
    for (int i=threadIdx.x;i<16*DM;i+=blockDim.x) xt[i]=x[(size_t)tb*DM+i];
    __syncthreads();
    int j = threadIdx.x;
    u64 acc[16];
#pragma unroll
    for(int t=0;t<16;t++) acc[t]=0ull;
    const float4* w4 = reinterpret_cast<const float4*>(w + j*DM);
#pragma unroll
    for(int c4=0;c4<DM/4;c4++){
        F4U wv; wv.f = w4[c4];
#pragma unroll
        for(int t=0;t<16;t++){
            F4U xv; xv.f = *reinterpret_cast<const float4*>(&xt[t*DM+c4*4]);
            acc[t]=fma2(wv.u[0],xv.u[0],acc[t]);
            acc[t]=fma2(wv.u[1],xv.u[1],acc[t]);
        }
    }
    if(j<DI){
#pragma unroll
        for(int t=0;t<16;t++) g_xcraw[(size_t)(tb+t)*DI+j]=LOF(acc[t])+HIF(acc[t]);
    } else {
        int jz=j-DI;
#pragma unroll
        for(int t=0;t<16;t++) g_z[(size_t)(tb+t)*DI+jz]=fsilu(LOF(acc[t])+HIF(acc[t]));
    }
}

/* ------------- fused conv + x_proj + dt_proj + delta (TT=16 tile) ------------- */
__global__ __launch_bounds__(256) void k_mid(
    const float* __restrict__ cw, const float* __restrict__ cb,
    const float* __restrict__ xw,
    const float* __restrict__ dtw_g, const float* __restrict__ dtb_g,
    const float* __restrict__ alog)
{
    __shared__ float sxc[TT*DI];
    __shared__ float stage[KK*TT][40];
    int b  = blockIdx.y;
    int l0 = blockIdx.x * TT;
    int tid = threadIdx.x;

    if (tid < DI){
        int d = tid;
        float wt[9];
#pragma unroll
        for(int i=0;i<9;i++) wt[i]=cw[d*9+i];
        float bias=cb[d];
        const float* base = g_xcraw + (size_t)b*LL*DI + d;
        float* xo = g_xch + ((size_t)b*LL + l0)*DI + d;
#pragma unroll 4
        for(int t=0;t<TT;t++){
            int l=l0+t, h=l/WW, w0=l%WW;
            float s=bias;
#pragma unroll
            for(int kh=0;kh<3;kh++){
                int h2=h+kh-1;
                if((unsigned)h2>=HH) continue;
#pragma unroll
                for(int kw=0;kw<3;kw++){
                    int w2=w0+kw-1;
                    if((unsigned)w2>=WW) continue;
                    s += base[(size_t)(h2*WW+w2)*DI]*wt[kh*3+kw];
                }
            }
            float v=fsilu(s);
            sxc[t*DI+d]=v;
            xo[(size_t)t*DI]=v;
        }
    }
    __syncthreads();

    if (tid < 228){
        int j = tid % 114;
        int t0 = (tid >= 114) ? 8 : 0;
        int k = j/38, c = j%38;
        u64 acc[8];
#pragma unroll
        for(int t=0;t<8;t++) acc[t]=0ull;
        const float4* w4 = reinterpret_cast<const float4*>(xw + (size_t)(k*38+c)*DI);
        for(int d4=0; d4<DI/4; d4++){
            F4U wv; wv.f=w4[d4];
#pragma unroll
            for(int t=0;t<8;t++){
                F4U xv; xv.f=*reinterpret_cast<const float4*>(&sxc[(t0+t)*DI+d4*4]);
                acc[t]=fma2(wv.u[0],xv.u[0],acc[t]);
                acc[t]=fma2(wv.u[1],xv.u[1],acc[t]);
            }
        }
        int slot = (c<RR)? c : (c<RR+NS ? 8+(c-RR) : 24+(c-RR-NS));
#pragma unroll
        for(int t=0;t<8;t++) stage[k*TT+t0+t][slot]=LOF(acc[t])+HIF(acc[t]);
    }
    __syncthreads();

    if (tid < DI){
        int d = tid;
#pragma unroll
        for(int k=0;k<KK;k++){
            float dtw[RR];
#pragma unroll
            for(int r=0;r<RR;r++) dtw[r]=dtw_g[(size_t)(k*DI+d)*RR+r];
            float bias=dtb_g[k*DI+d];
            float A0 = -__expf(alog[(size_t)(k*DI+d)*NS]);
            float2* pb = g_pre + ((size_t)(b*KK+k)*LL)*DI + d;
#pragma unroll 4
            for(int t=0;t<TT;t++){
                int lsp=l0+t;
                int p = (k==0)? lsp : (k==1 ? (lsp%WW)*HH + lsp/WW : LL-1-lsp);
                float s=bias;
#pragma unroll
                for(int r=0;r<RR;r++) s += dtw[r]*stage[k*TT+t][r];
                float dt = fmaxf(s,0.f) + __logf(1.f + __expf(-fabsf(s)));
                float e1 = __expf(dt * A0);
                pb[(size_t)p*DI] = make_float2(e1, dt*sxc[t*DI+d]);
            }
        }
    }

    for(int i=tid; i<KK*TT*XD; i+=256){
        int row=i/XD, j=i%XD;
        int k=row/TT, t=row%TT;
        int lsp=l0+t;
        int p = (k==0)? lsp : (k==1 ? (lsp%WW)*HH + lsp/WW : LL-1-lsp);
        g_xdbl[((size_t)(b*KK+k)*LL+p)*XD + j] = stage[row][8+j];
    }
}

/* tree powers: a[j] = (e1^(2j+1), e1^(2j+2)) */
__device__ __forceinline__ void tree_pow(float e1, u64 a[8]){
    float e2=e1*e1, e4=e2*e2, e8=e4*e4;
    u64 e2p=F2P(e2,e2), e4p=F2P(e4,e4), e8p=F2P(e8,e8);
    a[0]=F2P(e1,e2);
    a[1]=mul2(a[0],e2p);
    a[2]=mul2(a[0],e4p);
    a[3]=mul2(a[1],e4p);
    a[4]=mul2(a[0],e8p);
    a[5]=mul2(a[1],e8p);
    a[6]=mul2(a[2],e8p);
    a[7]=mul2(a[3],e8p);
}

/* one unit-path scan step (states packed in h2[8]) */
__device__ __forceinline__ void scan_step1(float2 ed, const float* sbrow, u64 h2[8]){
    u64 du2=F2P(ed.y,ed.y);
    u64 a[8]; tree_pow(ed.x, a);
    const F4U* bp=reinterpret_cast<const F4U*>(sbrow);
#pragma unroll
    for(int j=0;j<4;j++){
        F4U bv=bp[j];
        h2[2*j]  = fma2(a[2*j],  h2[2*j],  mul2(du2,bv.u[0]));
        h2[2*j+1]= fma2(a[2*j+1],h2[2*j+1],mul2(du2,bv.u[1]));
    }
}

/* ------------- scan pass 1: segment summaries, h0=0 (PF=2 prefetch) ------------- */
__global__ __launch_bounds__(DI, 6) void k_scan1(const float* __restrict__ alog)
{
    __shared__ float sb[LSEG*32];
    int seg = blockIdx.x, bk = blockIdx.y;
    int d = threadIdx.x;
    int chain = bk*DI + d;
    int k = bk % KK;
    int l0 = seg*LSEG;
    {
        const float4* src = reinterpret_cast<const float4*>(g_xdbl + ((size_t)bk*LL + l0)*XD);
        for(int i=threadIdx.x;i<LSEG*8;i+=blockDim.x)
            reinterpret_cast<float4*>(sb)[i]=src[i];
    }
    __syncthreads();

    const float* ar = alog + (size_t)(k*DI+d)*NS;
    float a0 = ar[0];
    bool unit=true;
#pragma unroll
    for(int n=0;n<NS;n++){
        float r=__expf(ar[n]-a0);
        unit = unit && (fabsf(r-(float)(n+1))<1e-3f);
    }
    bool wunit = __all_sync(0xffffffffu, unit);
    const float2* pre = g_pre + (size_t)bk*LL*DI + d;
    float pe=1.f;
    if(wunit){
        u64 h2[8];
#pragma unroll
        for(int j=0;j<8;j++) h2[j]=0ull;
        float2 c0=pre[(size_t)l0*DI], c1=pre[(size_t)(l0+1)*DI];
#pragma unroll
        for(int io=0;io<LSEG;io+=2){
            float2 n0=c0, n1=c1;
            if(io+2<LSEG){ n0=pre[(size_t)(l0+io+2)*DI]; n1=pre[(size_t)(l0+io+3)*DI]; }
            pe*=c0.x; scan_step1(c0, &sb[io*32], h2);
            pe*=c1.x; scan_step1(c1, &sb[(io+1)*32], h2);
            c0=n0; c1=n1;
        }
#pragma unroll
        for(int j=0;j<8;j++){
            g_segq[seg][2*j][chain]  =LOF(h2[j]);
            g_segq[seg][2*j+1][chain]=HIF(h2[j]);
        }
    } else {
        float rn[NS], h[NS];
#pragma unroll
        for(int n=0;n<NS;n++){ rn[n]=__expf(ar[n]-a0); h[n]=0.f; }
        for(int i=0;i<LSEG;i++){
            float2 ed=pre[(size_t)(l0+i)*DI];
            pe*=ed.x;
            float lg=__log2f(ed.x), du=ed.y;
#pragma unroll
            for(int n=0;n<NS;n++)
                h[n]=exp2f(lg*rn[n])*h[n] + du*sb[i*32+n];
        }
#pragma unroll
        for(int n=0;n<NS;n++) g_segq[seg][n][chain]=h[n];
    }
    g_segp[seg][chain]=pe;
}

/* ------------- combine: two-level parallel prefix (8 threads per chain-state) ------------- */
__global__ __launch_bounds__(256) void k_comb(const float* __restrict__ alog)
{
    int gt = blockIdx.x*256 + threadIdx.x;   /* CH*NS*8 threads */
    int t  = gt & 7;
    int cn = gt >> 3;
    int chain = cn % CH;
    int n  = cn / CH;
    int d = chain % DI, k = (chain / DI) % KK;
    const float* ar = alog + (size_t)(k*DI+d)*NS;
    float ratio = __expf(ar[n] - ar[0]);
    float rf = rintf(ratio);
    int   m  = (int)rf;
    bool exact = (fabsf(ratio-rf) < 1e-3f) && m >= 1 && m <= 31;
    int s0 = t*8;
    float A=1.f, Q=0.f;
    float Ap[8], Qp[8];
#pragma unroll
    for(int i=0;i<8;i++){
        Ap[i]=A; Qp[i]=Q;
        float pe = __ldg(&g_segp[s0+i][chain]);
        float q  = __ldg(&g_segq[s0+i][n][chain]);
        float a;
        if (exact){
            float pe2=pe*pe, pe4=pe2*pe2, pe8=pe4*pe4, pe16=pe8*pe8;
            a = (m&1)? pe : 1.f;
            if(m&2)  a*=pe2;
            if(m&4)  a*=pe4;
            if(m&8)  a*=pe8;
            if(m&16) a*=pe16;
        } else {
            a = exp2f(__log2f(pe)*ratio);
        }
        A = a*A;
        Q = a*Q + q;
    }
#pragma unroll
    for(int dlt=1; dlt<8; dlt<<=1){
        float Apv = __shfl_up_sync(0xffffffffu, A, dlt, 8);
        float Qpv = __shfl_up_sync(0xffffffffu, Q, dlt, 8);
        if (t >= dlt){ Q = A*Qpv + Q; A = A*Apv; }
    }
    float hin = __shfl_up_sync(0xffffffffu, Q, 1, 8);
    if (t == 0) hin = 0.f;
#pragma unroll
    for(int i=0;i<8;i++)
        g_hin[s0+i][n][chain] = Ap[i]*hin + Qp[i];
}

/* ------------- scan pass 2: rescan with h_init, emit y (PF=2 prefetch) ------------- */
__global__ __launch_bounds__(DI, 6) void k_scan2(const float* __restrict__ alog)
{
    __shared__ float sb[LSEG*32];
    int seg=blockIdx.x, bk=blockIdx.y;
    int d=threadIdx.x;
    int chain=bk*DI+d;
    int k=bk%KK, b=bk/KK;
    int l0=seg*LSEG;
    {
        const float4* src = reinterpret_cast<const float4*>(g_xdbl + ((size_t)bk*LL + l0)*XD);
        for(int i=threadIdx.x;i<LSEG*8;i+=blockDim.x)
            reinterpret_cast<float4*>(sb)[i]=src[i];
    }
    __syncthreads();
    const float* ar=alog+(size_t)(k*DI+d)*NS;
    float a0=ar[0];
    bool unit=true;
#pragma unroll
    for(int n=0;n<NS;n++){ float r=__expf(ar[n]-a0); unit=unit&&(fabsf(r-(float)(n+1))<1e-3f); }
    bool wunit=__all_sync(0xffffffffu,unit);
    const float2* pre=g_pre+(size_t)bk*LL*DI+d;
    float* yout=g_ys[k]+(size_t)b*LL*DI+d;
    int hh=l0%HH, wc=l0/HH;
    if(wunit){
        u64 h2[8];
#pragma unroll
        for(int j=0;j<8;j++) h2[j]=F2P(g_hin[seg][2*j][chain], g_hin[seg][2*j+1][chain]);
        float2 c0=pre[(size_t)l0*DI], c1=pre[(size_t)(l0+1)*DI];
        for(int io=0;io<LSEG;io+=2){
            float2 n0=c0, n1=c1;
            if(io+2<LSEG){ n0=pre[(size_t)(l0+io+2)*DI]; n1=pre[(size_t)(l0+io+3)*DI]; }
#pragma unroll
            for(int half=0; half<2; half++){
                float2 ed = half? c1 : c0;
                int i = io + half;
                u64 du2=F2P(ed.y,ed.y);
                u64 a[8]; tree_pow(ed.x, a);
                const F4U* bp=reinterpret_cast<const F4U*>(&sb[i*32]);
                const F4U* cp=reinterpret_cast<const F4U*>(&sb[i*32+16]);
                u64 ya=0ull, yb=0ull;
#pragma unroll
                for(int j=0;j<4;j++){
                    F4U bv=bp[j]; F4U cv=cp[j];
                    h2[2*j]  =fma2(a[2*j],  h2[2*j],  mul2(du2,bv.u[0])); ya=fma2(h2[2*j],  cv.u[0],ya);
                    h2[2*j+1]=fma2(a[2*j+1],h2[2*j+1],mul2(du2,bv.u[1])); yb=fma2(h2[2*j+1],cv.u[1],yb);
                }
                float y=LOF(ya)+HIF(ya)+LOF(yb)+HIF(yb);
                int l=l0+i, pos;
                if(k==0) pos=l;
                else if(k==1){ pos=hh*WW+wc; hh++; if(hh==HH){hh=0;wc++;} }
                else pos=LL-1-l;
                yout[(size_t)pos*DI]=y;
            }
            c0=n0; c1=n1;
        }
    } else {
        float rn[NS],h[NS];
#pragma unroll
        for(int n=0;n<NS;n++){ rn[n]=__expf(ar[n]-a0); h[n]=g_hin[seg][n][chain]; }
        for(int i=0;i<LSEG;i++){
            float2 ed=pre[(size_t)(l0+i)*DI];
            float lg=__log2f(ed.x), du=ed.y, y=0.f;
#pragma unroll
            for(int n=0;n<NS;n++){
                h[n]=exp2f(lg*rn[n])*h[n]+du*sb[i*32+n];
                y+=h[n]*sb[i*32+16+n];
            }
            int l=l0+i,pos;
            if(k==0)pos=l;
            else if(k==1){pos=hh*WW+wc;hh++;if(hh==HH){hh=0;wc++;}}
            else pos=LL-1-l;
            yout[(size_t)pos*DI]=y;
        }
    }
}

/* ------------- merge (vectorized) + D-term + gating + out_proj ------------- */
__global__ __launch_bounds__(128) void k_out(const float* __restrict__ ow, const float* __restrict__ Ds,
                                             float* __restrict__ out)
{
    __shared__ float yz[16*DI];
    __shared__ float dsum_s[DI];
    int tid=threadIdx.x;
    int tb=blockIdx.x*16;
    size_t base4=(size_t)tb*DI/4;
    for(int i=tid;i<DI;i+=128) dsum_s[i]=Ds[i]+Ds[DI+i]+Ds[2*DI+i];
    __syncthreads();
    {
        const float4* y0=reinterpret_cast<const float4*>(g_ys[0])+base4;
        const float4* y1=reinterpret_cast<const float4*>(g_ys[1])+base4;
        const float4* y2=reinterpret_cast<const float4*>(g_ys[2])+base4;
        const float4* xc=reinterpret_cast<const float4*>(g_xch)+base4;
        const float4* zz=reinterpret_cast<const float4*>(g_z)+base4;
#pragma unroll
        for(int it=0; it<6; it++){
            int i4 = tid + it*128;
            int dd4=(i4*4)%DI;
            float4 a=y0[i4], b=y1[i4], c=y2[i4], x=xc[i4], z=zz[i4];
            float4 ds=*reinterpret_cast<const float4*>(&dsum_s[dd4]);
            float4 v;
            v.x=(a.x+b.x+c.x+ds.x*x.x)*z.x;
            v.y=(a.y+b.y+c.y+ds.y*x.y)*z.y;
            v.z=(a.z+b.z+c.z+ds.z*x.z)*z.z;
            v.w=(a.w+b.w+c.w+ds.w*x.w)*z.w;
            *reinterpret_cast<float4*>(&yz[i4*4])=v;
        }
    }
    __syncthreads();
    int j=tid;
    if(j<DM){
        u64 acc[16];
#pragma unroll
        for(int t=0;t<16;t++) acc[t]=0ull;
        const float4* w4=reinterpret_cast<const float4*>(ow+(size_t)j*DI);
        for(int d4=0;d4<DI/4;d4++){
            F4U wv; wv.f=w4[d4];
#pragma unroll
            for(int t=0;t<16;t++){
                F4U xv; xv.f=*reinterpret_cast<const float4*>(&yz[t*DI+d4*4]);
                acc[t]=fma2(wv.u[0],xv.u[0],acc[t]);
                acc[t]=fma2(wv.u[1],xv.u[1],acc[t]);
            }
        }
#pragma unroll
        for(int t=0;t<16;t++) out[(size_t)(tb+t)*DM+j]=LOF(acc[t])+HIF(acc[t]);
    }
}

/* ---------------- launcher ---------------- */
extern "C" void kernel_launch(void* const* d_in, const int* in_sizes, int n_in,
                              void* d_out, int out_size)
{
    const float* x    = (const float*)d_in[0];
    const float* inw  = (const float*)d_in[2];
    const float* cw   = (const float*)d_in[3];
    const float* cb   = (const float*)d_in[4];
    const float* xw   = (const float*)d_in[5];
    const float* dtw  = (const float*)d_in[6];
    const float* dtb  = (const float*)d_in[7];
    const float* alog = (const float*)d_in[8];
    const float* Ds   = (const float*)d_in[9];
    const float* ow   = (const float*)d_in[10];
    float* out = (float*)d_out;

    k_inproj<<<BB*LL/16, 384>>>(x, inw);
    k_mid   <<<dim3(LL/TT, BB), 256>>>(cw, cb, xw, dtw, dtb, alog);
    k_scan1 <<<dim3(SS, BB*KK), DI>>>(alog);
    k_comb  <<<CH*NS*8/256, 256>>>(alog);
    k_scan2 <<<dim3(SS, BB*KK), DI>>>(alog);
    k_out   <<<BB*LL/16, 128>>>(ow, Ds, out);
}